// round 2
// baseline (speedup 1.0000x reference)
#include <cuda_runtime.h>
#include <cstdint>

#define BB   16
#define NN   8192
#define KNB  16
#define MTOT (BB*NN)      // 131072
#define H3   64
#define H2   128
#define H1   512
#define EPSBN 1e-5f

typedef unsigned long long ull;
typedef unsigned int uint;

// ---------------- scratch (static device globals; no allocs allowed) ----------------
__device__ float g_pre1[MTOT*H3];
__device__ float g_agg1[MTOT*H3];
__device__ float g_pre2[MTOT*H2];
__device__ float g_agg2[MTOT*H2];
__device__ float g_z2[MTOT*3];
__device__ float g_sum1[H3], g_sq1[H3];
__device__ float g_sum2[H2], g_sq2[H2];
__device__ float g_sum3[H1], g_sq3[H1];
__device__ uint  g_maxk[BB*H1], g_mink[BB*H1];
__device__ float g_bn1[2*H3];
__device__ float g_bn2[2*H2];
__device__ float g_pool[BB*H1];
__device__ float g_pre4[BB*H1];
__device__ float g_dc1[BB*3], g_dc2[BB*3];
__device__ float g_d1p[6];
__device__ float g_sumd[3], g_sqd[3];

// ---------------- helpers ----------------
__device__ __forceinline__ uint fkey(float f){
    uint u = __float_as_uint(f);
    return (u & 0x80000000u) ? ~u : (u | 0x80000000u);
}
__device__ __forceinline__ float keyf(uint k){
    uint u = (k & 0x80000000u) ? (k ^ 0x80000000u) : ~k;
    return __uint_as_float(u);
}
__device__ __forceinline__ float2 unpack2(ull v){
    float2 f; asm("mov.b64 {%0,%1}, %2;" : "=f"(f.x), "=f"(f.y) : "l"(v)); return f;
}
__device__ __forceinline__ void ffma2(ull &d, ull a, ull b){
    asm("fma.rn.f32x2 %0, %1, %2, %0;" : "+l"(d) : "l"(a), "l"(b));
}

// ---------------- kernels ----------------
__global__ void k_zero(){
    int i = blockIdx.x*blockDim.x + threadIdx.x;
    if (i < BB*H1){ g_maxk[i]=0u; g_mink[i]=0xFFFFFFFFu; }
    if (i < H1){ g_sum3[i]=0.f; g_sq3[i]=0.f; }
    if (i < H2){ g_sum2[i]=0.f; g_sq2[i]=0.f; }
    if (i < H3){ g_sum1[i]=0.f; g_sq1[i]=0.f; }
    if (i < 3){ g_sumd[i]=0.f; g_sqd[i]=0.f; }
}

// covariance features + Linear(12,64) + BN stats
__global__ __launch_bounds__(256) void k_cov_e1(
    const float* __restrict__ data, const int* __restrict__ knn,
    const float* __restrict__ w, const float* __restrict__ bias)
{
    __shared__ float Ws[12*H3];
    __shared__ float bs[H3];
    __shared__ float x0s[256*12];
    __shared__ float ssum[H3], ssq[H3];
    int t = threadIdx.x;
    for (int i = t; i < 12*H3; i += 256) Ws[i] = w[i];
    if (t < H3){ bs[t] = bias[t]; ssum[t]=0.f; ssq[t]=0.f; }

    int gi = blockIdx.x*256 + t;
    int b = gi >> 13;
    const int* kp = knn + (size_t)gi*KNB;
    float sx=0,sy=0,sz=0,sxx=0,sxy=0,sxz=0,syy=0,syz=0,szz=0;
    #pragma unroll
    for (int k=0;k<KNB;k++){
        int j = kp[k];
        const float* p = data + ((size_t)(b*NN + j))*3;
        float x=p[0], y=p[1], z=p[2];
        sx+=x; sy+=y; sz+=z;
        sxx+=x*x; sxy+=x*y; sxz+=x*z; syy+=y*y; syz+=y*z; szz+=z*z;
    }
    float mx=sx*(1.f/16.f), my=sy*(1.f/16.f), mz=sz*(1.f/16.f);
    const float i15 = 1.f/15.f;
    float cxx=(sxx-16.f*mx*mx)*i15, cxy=(sxy-16.f*mx*my)*i15, cxz=(sxz-16.f*mx*mz)*i15;
    float cyy=(syy-16.f*my*my)*i15, cyz=(syz-16.f*my*mz)*i15, czz=(szz-16.f*mz*mz)*i15;
    float* xr = &x0s[t*12];
    xr[0]=data[(size_t)gi*3+0]; xr[1]=data[(size_t)gi*3+1]; xr[2]=data[(size_t)gi*3+2];
    xr[3]=cxx; xr[4]=cxy; xr[5]=cxz; xr[6]=cxy; xr[7]=cyy; xr[8]=cyz; xr[9]=cxz; xr[10]=cyz; xr[11]=czz;
    __syncthreads();

    int c = t & 63;
    float bsum=0.f, bsq=0.f;
    float* outp = g_pre1 + (size_t)blockIdx.x*256*H3;
    #pragma unroll 4
    for (int kq=0;kq<64;kq++){
        int e = t + kq*256;
        const float* x0 = &x0s[(e>>6)*12];
        float v = bs[c];
        #pragma unroll
        for (int j=0;j<12;j++) v = fmaf(x0[j], Ws[j*H3+c], v);
        outp[e] = v;
        bsum += v; bsq += v*v;
    }
    atomicAdd(&ssum[c], bsum); atomicAdd(&ssq[c], bsq);
    __syncthreads();
    if (t < H3){ atomicAdd(&g_sum1[t], ssum[t]); atomicAdd(&g_sq1[t], ssq[t]); }
}

template<int C, int LAYER>
__global__ void k_fin(const float* __restrict__ g, const float* __restrict__ be){
    int c = threadIdx.x;
    const float* su = (LAYER==1)? g_sum1 : g_sum2;
    const float* sq = (LAYER==1)? g_sq1  : g_sq2;
    float* bn = (LAYER==1)? g_bn1 : g_bn2;
    float invM = 1.f/(float)MTOT;
    float m = su[c]*invM;
    float v = fmaxf(sq[c]*invM - m*m, 0.f);
    float sc = g[c]*rsqrtf(v+EPSBN);
    bn[c]=sc; bn[C+c]= fmaf(-m, sc, be[c]);
}

// BN+ReLU on the fly, aggregate self + 16 neighbors, /17. float4 per thread.
template<int C, int LAYER>
__global__ __launch_bounds__(256) void k_agg(const int* __restrict__ knn){
    const int TPN = C/4;          // threads per node
    const int NPB = 256/TPN;      // nodes per block
    __shared__ int sidx[NPB][KNB];
    int t = threadIdx.x;
    int n0 = blockIdx.x*NPB;
    if (t < NPB*KNB) sidx[t>>4][t&15] = knn[(size_t)(n0 + (t>>4))*KNB + (t&15)];
    __syncthreads();
    int nl = t / TPN; int c4 = t % TPN;
    int gi = n0 + nl;
    int base = (gi >> 13) * NN;
    const float4* pre = (const float4*)((LAYER==1)? g_pre1 : g_pre2);
    const float*  bn  = (LAYER==1)? g_bn1  : g_bn2;
    float4* agg = (float4*)((LAYER==1)? g_agg1 : g_agg2);
    float4 sc = ((const float4*)bn)[c4];
    float4 sh = ((const float4*)bn)[TPN + c4];
    float4 p = pre[(size_t)gi*TPN + c4];
    float ax = fmaxf(fmaf(p.x, sc.x, sh.x), 0.f);
    float ay = fmaxf(fmaf(p.y, sc.y, sh.y), 0.f);
    float az = fmaxf(fmaf(p.z, sc.z, sh.z), 0.f);
    float aw = fmaxf(fmaf(p.w, sc.w, sh.w), 0.f);
    #pragma unroll
    for (int k=0;k<KNB;k++){
        int nb = base + sidx[nl][k];
        float4 q = pre[(size_t)nb*TPN + c4];
        ax += fmaxf(fmaf(q.x, sc.x, sh.x), 0.f);
        ay += fmaxf(fmaf(q.y, sc.y, sh.y), 0.f);
        az += fmaxf(fmaf(q.z, sc.z, sh.z), 0.f);
        aw += fmaxf(fmaf(q.w, sc.w, sh.w), 0.f);
    }
    const float s = 1.f/17.f;
    agg[(size_t)gi*TPN + c4] = make_float4(ax*s, ay*s, az*s, aw*s);
}

// tiled GEMM: 128 nodes x 128 ch per block, BK=16, duplicated-A smem for f32x2,
// fused BN stats (+per-batch minmax, no output write for layer 2)
template<int CIN, int COUT, bool WOUT, bool MM, int LAYER>
__global__ __launch_bounds__(256) void k_gemm(const float* __restrict__ W, const float* __restrict__ bias){
    const int BK = 16;
    const int ASTR2 = 260;                       // 128 nodes duplicated (256) + pad, 16B-aligned rows
    __shared__ __align__(16) float As2[BK*ASTR2];
    __shared__ __align__(16) float Ws[BK*128];
    __shared__ float ssum[128], ssq[128];
    __shared__ uint smx[128], smn[128];
    const float* in = (LAYER==1)? g_agg1 : g_agg2;
    float* sumg = (LAYER==1)? g_sum2 : g_sum3;
    float* sqg  = (LAYER==1)? g_sq2  : g_sq3;
    int t = threadIdx.x;
    int n0 = blockIdx.x*128;
    int cb = blockIdx.y*128;
    int cq = (t & 15)*8;        // 8 output cols
    int nb = (t >> 4)*8;        // 8 nodes
    if (t < 128){ ssum[t]=0.f; ssq[t]=0.f; if (MM){ smx[t]=0u; smn[t]=0xFFFFFFFFu; } }
    ull acc[8][4];
    #pragma unroll
    for (int n=0;n<8;n++){ acc[n][0]=0ull; acc[n][1]=0ull; acc[n][2]=0ull; acc[n][3]=0ull; }

    const int fL = t & (BK-1);      // loader feat
    const int nL = t >> 4;          // loader node group 0..15 (8 nodes each)

    for (int kk=0; kk<CIN; kk+=BK){
        // A tile: 128 nodes x BK feats, stored duplicated (a,a)
        #pragma unroll
        for (int i=0;i<8;i++){
            int node = nL + 16*i;
            float v = in[(size_t)(n0 + node)*CIN + kk + fL];
            *(float2*)&As2[fL*ASTR2 + 2*node] = make_float2(v, v);
        }
        // W tile: BK x 128
        #pragma unroll
        for (int i=0;i<8;i++){
            int idx = t + 256*i;
            int f = idx >> 7; int c = idx & 127;
            Ws[f*128 + c] = W[(size_t)(kk+f)*COUT + cb + c];
        }
        __syncthreads();
        #pragma unroll
        for (int f=0; f<BK; f++){
            const ull* Wp = (const ull*)&Ws[f*128 + cq];
            ull w0 = Wp[0], w1 = Wp[1], w2 = Wp[2], w3 = Wp[3];
            const ull* Ap = (const ull*)&As2[f*ASTR2 + 2*nb];
            #pragma unroll
            for (int n=0;n<8;n++){
                ull a2 = Ap[n];
                ffma2(acc[n][0], a2, w0);
                ffma2(acc[n][1], a2, w1);
                ffma2(acc[n][2], a2, w2);
                ffma2(acc[n][3], a2, w3);
            }
        }
        __syncthreads();
    }

    float bv[8], s[8], q[8], mx[8], mn[8];
    #pragma unroll
    for (int j=0;j<8;j++){ bv[j]=bias[cb+cq+j]; s[j]=0.f; q[j]=0.f; mx[j]=-3.402823466e38f; mn[j]=3.402823466e38f; }
    #pragma unroll
    for (int n=0;n<8;n++){
        float v[8];
        #pragma unroll
        for (int h=0;h<4;h++){
            float2 p = unpack2(acc[n][h]);
            v[2*h] = p.x + bv[2*h]; v[2*h+1] = p.y + bv[2*h+1];
        }
        #pragma unroll
        for (int j=0;j<8;j++){
            s[j]+=v[j]; q[j]+=v[j]*v[j];
            if (MM){ mx[j]=fmaxf(mx[j],v[j]); mn[j]=fminf(mn[j],v[j]); }
        }
        if (WOUT){
            *(float4*)(&g_pre2[(size_t)(n0+nb+n)*COUT + cb + cq])     = make_float4(v[0],v[1],v[2],v[3]);
            *(float4*)(&g_pre2[(size_t)(n0+nb+n)*COUT + cb + cq + 4]) = make_float4(v[4],v[5],v[6],v[7]);
        }
    }
    #pragma unroll
    for (int j=0;j<8;j++){
        atomicAdd(&ssum[cq+j], s[j]); atomicAdd(&ssq[cq+j], q[j]);
        if (MM){ atomicMax(&smx[cq+j], fkey(mx[j])); atomicMin(&smn[cq+j], fkey(mn[j])); }
    }
    __syncthreads();
    if (t < 128){
        atomicAdd(&sumg[cb+t], ssum[t]);
        atomicAdd(&sqg [cb+t], ssq[t]);
        if (MM){
            int b = n0 >> 13;
            atomicMax(&g_maxk[b*H1 + cb + t], smx[t]);
            atomicMin(&g_mink[b*H1 + cb + t], smn[t]);
        }
    }
}

// finalize BN3 + pooled = relu(max over nodes of BN'd value)
__global__ void k_fin3pool(const float* __restrict__ g, const float* __restrict__ be){
    int c = threadIdx.x;
    int b = blockIdx.x;
    float invM = 1.f/(float)MTOT;
    float m = g_sum3[c]*invM;
    float v = fmaxf(g_sq3[c]*invM - m*m, 0.f);
    float sc = g[c]*rsqrtf(v+EPSBN);
    float sh = fmaf(-m, sc, be[c]);
    float mx = keyf(g_maxk[b*H1+c]);
    float mn = keyf(g_mink[b*H1+c]);
    float val = (sc >= 0.f) ? fmaf(mx, sc, sh) : fmaf(mn, sc, sh);
    g_pool[b*H1+c] = fmaxf(val, 0.f);
}

// e2 linear: pre4[b] = pool[b] @ W + bias   (block per batch)
__global__ __launch_bounds__(512) void k_e2(const float* __restrict__ W, const float* __restrict__ bias){
    __shared__ float sp[H1];
    int b = blockIdx.x, c = threadIdx.x;
    sp[c] = g_pool[b*H1 + c];
    __syncthreads();
    float acc = bias[c];
    #pragma unroll 4
    for (int f=0; f<H1; f++) acc = fmaf(sp[f], W[(size_t)f*H1 + c], acc);
    g_pre4[b*H1 + c] = acc;
}

// e2 BN(M=16)+ReLU -> code; decoder per-batch dots; analytic d1 BN params
__global__ __launch_bounds__(512) void k_code2(
    const float* __restrict__ eg, const float* __restrict__ ebe,
    const float* __restrict__ d1w, const float* __restrict__ d1b,
    const float* __restrict__ d1g, const float* __restrict__ d1be,
    const float* __restrict__ d2w, const float* __restrict__ d2b)
{
    __shared__ float scm[BB*H1];
    int t = threadIdx.x;
    float vals[16]; float s = 0.f;
    #pragma unroll
    for (int b=0;b<16;b++){ vals[b]=g_pre4[b*H1+t]; s+=vals[b]; }
    float m = s*(1.f/16.f);
    float q = 0.f;
    #pragma unroll
    for (int b=0;b<16;b++){ float d=vals[b]-m; q+=d*d; }
    float scl = eg[t]*rsqrtf(q*(1.f/16.f)+EPSBN);
    float sh = ebe[t];
    #pragma unroll
    for (int b=0;b<16;b++) scm[b*H1+t] = fmaxf(fmaf(vals[b]-m, scl, sh), 0.f);
    __syncthreads();

    int w = t>>5, lane = t&31;
    if (w < 6){
        for (int d = w*16; d < w*16+16; d++){
            int layer = d/48; int r = d%48; int b = r/3; int c = r%3;
            const float* Wd = layer ? d2w : d1w;
            float p = 0.f;
            for (int f=lane; f<H1; f+=32) p = fmaf(scm[b*H1+f], Wd[f*3+c], p);
            #pragma unroll
            for (int o=16;o;o>>=1) p += __shfl_xor_sync(0xffffffffu, p, o);
            if (lane==0){
                if (layer) g_dc2[b*3+c] = p + d2b[c];
                else       g_dc1[b*3+c] = p + d1b[c];
            }
        }
    }
    __syncthreads();
    if (w < 3){
        float wx = d1w[1536 + w], wy = d1w[1539 + w];
        float sG = 0.f;
        for (int n=lane; n<NN; n+=32){
            int ix = n/65, iy = n - ix*65;
            float gx = 1.f + ix*(119.f/128.f);
            float gy = 1.f + iy*(59.f/64.f);
            sG += gx*wx + gy*wy;
        }
        #pragma unroll
        for (int o=16;o;o>>=1) sG += __shfl_xor_sync(0xffffffffu, sG, o);
        float mG = sG*(1.f/8192.f);
        float qG = 0.f;
        for (int n=lane; n<NN; n+=32){
            int ix = n/65, iy = n - ix*65;
            float gx = 1.f + ix*(119.f/128.f);
            float gy = 1.f + iy*(59.f/64.f);
            float d = gx*wx + gy*wy - mG;
            qG += d*d;
        }
        #pragma unroll
        for (int o=16;o;o>>=1) qG += __shfl_xor_sync(0xffffffffu, qG, o);
        if (lane==0){
            float vG = qG*(1.f/8192.f);
            float sA=0.f;
            #pragma unroll
            for (int b=0;b<16;b++) sA += g_dc1[b*3+w];
            float mA = sA*(1.f/16.f);
            float qA=0.f;
            #pragma unroll
            for (int b=0;b<16;b++){ float d=g_dc1[b*3+w]-mA; qA+=d*d; }
            float vA = qA*(1.f/16.f);
            float mean = mA + mG;
            float var = fmaxf(vA + vG, 0.f);
            float sc1 = d1g[w]*rsqrtf(var+EPSBN);
            g_d1p[w]=sc1; g_d1p[3+w]= d1be[w] - mean*sc1;
        }
    }
}

// per-node decode: z1 (d1+BN+ReLU), z2pre (d2), write z2pre + d2 BN stats
__global__ __launch_bounds__(256) void k_decode(const float* __restrict__ d1w, const float* __restrict__ d2w){
    __shared__ float ss[3], sq_[3];
    int t = threadIdx.x;
    if (t<3){ ss[t]=0.f; sq_[t]=0.f; }
    __syncthreads();
    int gi = blockIdx.x*256 + t;
    int n = gi & (NN-1);
    int b = gi >> 13;
    int ix = n/65, iy = n - ix*65;
    float gx = 1.f + ix*(119.f/128.f);
    float gy = 1.f + iy*(59.f/64.f);
    float z1[3];
    #pragma unroll
    for (int c=0;c<3;c++){
        float pre = g_dc1[b*3+c] + gx*d1w[1536+c] + gy*d1w[1539+c];
        z1[c] = fmaxf(fmaf(pre, g_d1p[c], g_d1p[3+c]), 0.f);
    }
    float v[3];
    #pragma unroll
    for (int c=0;c<3;c++){
        v[c] = g_dc2[b*3+c] + z1[0]*d2w[1536+c] + z1[1]*d2w[1539+c] + z1[2]*d2w[1542+c];
        g_z2[(size_t)gi*3+c] = v[c];
    }
    int lane = t & 31;
    #pragma unroll
    for (int c=0;c<3;c++){
        float sv = v[c], qv = v[c]*v[c];
        #pragma unroll
        for (int o=16;o;o>>=1){ sv += __shfl_xor_sync(0xffffffffu, sv, o); qv += __shfl_xor_sync(0xffffffffu, qv, o); }
        if (lane==0){ atomicAdd(&ss[c], sv); atomicAdd(&sq_[c], qv); }
    }
    __syncthreads();
    if (t<3){ atomicAdd(&g_sumd[t], ss[t]); atomicAdd(&g_sqd[t], sq_[t]); }
}

__global__ void k_out(float* __restrict__ out, const float* __restrict__ g, const float* __restrict__ be){
    int i = blockIdx.x*blockDim.x + threadIdx.x;
    if (i >= MTOT*3) return;
    int c = i % 3;
    float invM = 1.f/(float)MTOT;
    float m = g_sumd[c]*invM;
    float v = fmaxf(g_sqd[c]*invM - m*m, 0.f);
    float sc = g[c]*rsqrtf(v+EPSBN);
    out[i] = fmaxf(fmaf(g_z2[i]-m, sc, be[c]), 0.f);
}

// ---------------- launch ----------------
extern "C" void kernel_launch(void* const* d_in, const int* in_sizes, int n_in,
                              void* d_out, int out_size)
{
    const float* data = (const float*)d_in[0];
    const int*   knn  = (const int*)  d_in[1];
    const float* e1w  = (const float*)d_in[2];
    const float* e1b  = (const float*)d_in[3];
    const float* e1g  = (const float*)d_in[4];
    const float* e1be = (const float*)d_in[5];
    const float* gc1w = (const float*)d_in[6];
    const float* gc1b = (const float*)d_in[7];
    const float* g1g  = (const float*)d_in[8];
    const float* g1be = (const float*)d_in[9];
    const float* gc2w = (const float*)d_in[10];
    const float* gc2b = (const float*)d_in[11];
    const float* g2g  = (const float*)d_in[12];
    const float* g2be = (const float*)d_in[13];
    const float* e2w  = (const float*)d_in[14];
    const float* e2b  = (const float*)d_in[15];
    const float* e2g  = (const float*)d_in[16];
    const float* e2be = (const float*)d_in[17];
    const float* d1w  = (const float*)d_in[18];
    const float* d1b  = (const float*)d_in[19];
    const float* d1g  = (const float*)d_in[20];
    const float* d1be = (const float*)d_in[21];
    const float* d2w  = (const float*)d_in[22];
    const float* d2b  = (const float*)d_in[23];
    const float* d2g  = (const float*)d_in[24];
    const float* d2be = (const float*)d_in[25];
    float* out = (float*)d_out;

    k_zero<<<8, 1024>>>();
    k_cov_e1<<<MTOT/256, 256>>>(data, knn, e1w, e1b);
    k_fin<H3,1><<<1, H3>>>(e1g, e1be);
    k_agg<H3,1><<<MTOT/16, 256>>>(knn);
    k_gemm<H3,H2,true,false,1><<<dim3(MTOT/128,1), 256>>>(gc1w, gc1b);
    k_fin<H2,2><<<1, H2>>>(g1g, g1be);
    k_agg<H2,2><<<MTOT/8, 256>>>(knn);
    k_gemm<H2,H1,false,true,2><<<dim3(MTOT/128,4), 256>>>(gc2w, gc2b);
    k_fin3pool<<<BB, H1>>>(g2g, g2be);
    k_e2<<<BB, H1>>>(e2w, e2b);
    k_code2<<<1, 512>>>(e2g, e2be, d1w, d1b, d1g, d1be, d2w, d2b);
    k_decode<<<MTOT/256, 256>>>(d1w, d2w);
    k_out<<<(MTOT*3+255)/256, 256>>>(out, d2g, d2be);
}

// round 3
// speedup vs baseline: 1.2634x; 1.2634x over previous
#include <cuda_runtime.h>
#include <cstdint>

#define BB   16
#define NN   8192
#define KNB  16
#define MTOT (BB*NN)      // 131072
#define H3   64
#define H2   128
#define H1   512
#define EPSBN 1e-5f

typedef unsigned long long ull;
typedef unsigned int uint;

// ---------------- scratch (static device globals; no allocs allowed) ----------------
__device__ float g_pre1[MTOT*H3];
__device__ float g_agg1[MTOT*H3];
__device__ float g_pre2[MTOT*H2];
__device__ float g_agg2[MTOT*H2];
__device__ float g_z2[MTOT*3];
__device__ float g_sum1[H3], g_sq1[H3];
__device__ float g_sum2[H2], g_sq2[H2];
__device__ float g_sum3[H1], g_sq3[H1];
__device__ uint  g_maxk[BB*H1], g_mink[BB*H1];
__device__ float g_bn1[2*H3];
__device__ float g_bn2[2*H2];
__device__ float g_pool[BB*H1];
__device__ float g_pre4[BB*H1];
__device__ float g_dc1[BB*3], g_dc2[BB*3];
__device__ float g_d1p[6];
__device__ float g_sumd[3], g_sqd[3];

// ---------------- helpers ----------------
__device__ __forceinline__ uint fkey(float f){
    uint u = __float_as_uint(f);
    return (u & 0x80000000u) ? ~u : (u | 0x80000000u);
}
__device__ __forceinline__ float keyf(uint k){
    uint u = (k & 0x80000000u) ? (k ^ 0x80000000u) : ~k;
    return __uint_as_float(u);
}
__device__ __forceinline__ float2 unpack2(ull v){
    float2 f; asm("mov.b64 {%0,%1}, %2;" : "=f"(f.x), "=f"(f.y) : "l"(v)); return f;
}
__device__ __forceinline__ void ffma2(ull &d, ull a, ull b){
    asm("fma.rn.f32x2 %0, %1, %2, %0;" : "+l"(d) : "l"(a), "l"(b));
}

// ---------------- kernels ----------------
__global__ void k_zero(){
    int i = blockIdx.x*blockDim.x + threadIdx.x;
    if (i < BB*H1){ g_maxk[i]=0u; g_mink[i]=0xFFFFFFFFu; }
    if (i < H1){ g_sum3[i]=0.f; g_sq3[i]=0.f; }
    if (i < H2){ g_sum2[i]=0.f; g_sq2[i]=0.f; }
    if (i < H3){ g_sum1[i]=0.f; g_sq1[i]=0.f; }
    if (i < 3){ g_sumd[i]=0.f; g_sqd[i]=0.f; }
}

// covariance features + Linear(12,64) + BN stats
__global__ __launch_bounds__(256) void k_cov_e1(
    const float* __restrict__ data, const int* __restrict__ knn,
    const float* __restrict__ w, const float* __restrict__ bias)
{
    __shared__ float Ws[12*H3];
    __shared__ float bs[H3];
    __shared__ float x0s[256*12];
    __shared__ float ssum[H3], ssq[H3];
    int t = threadIdx.x;
    for (int i = t; i < 12*H3; i += 256) Ws[i] = w[i];
    if (t < H3){ bs[t] = bias[t]; ssum[t]=0.f; ssq[t]=0.f; }

    int gi = blockIdx.x*256 + t;
    int b = gi >> 13;
    const int* kp = knn + (size_t)gi*KNB;
    float sx=0,sy=0,sz=0,sxx=0,sxy=0,sxz=0,syy=0,syz=0,szz=0;
    #pragma unroll
    for (int k=0;k<KNB;k++){
        int j = kp[k];
        const float* p = data + ((size_t)(b*NN + j))*3;
        float x=p[0], y=p[1], z=p[2];
        sx+=x; sy+=y; sz+=z;
        sxx+=x*x; sxy+=x*y; sxz+=x*z; syy+=y*y; syz+=y*z; szz+=z*z;
    }
    float mx=sx*(1.f/16.f), my=sy*(1.f/16.f), mz=sz*(1.f/16.f);
    const float i15 = 1.f/15.f;
    float cxx=(sxx-16.f*mx*mx)*i15, cxy=(sxy-16.f*mx*my)*i15, cxz=(sxz-16.f*mx*mz)*i15;
    float cyy=(syy-16.f*my*my)*i15, cyz=(syz-16.f*my*mz)*i15, czz=(szz-16.f*mz*mz)*i15;
    float* xr = &x0s[t*12];
    xr[0]=data[(size_t)gi*3+0]; xr[1]=data[(size_t)gi*3+1]; xr[2]=data[(size_t)gi*3+2];
    xr[3]=cxx; xr[4]=cxy; xr[5]=cxz; xr[6]=cxy; xr[7]=cyy; xr[8]=cyz; xr[9]=cxz; xr[10]=cyz; xr[11]=czz;
    __syncthreads();

    int c = t & 63;
    float bsum=0.f, bsq=0.f;
    float* outp = g_pre1 + (size_t)blockIdx.x*256*H3;
    #pragma unroll 4
    for (int kq=0;kq<64;kq++){
        int e = t + kq*256;
        const float* x0 = &x0s[(e>>6)*12];
        float v = bs[c];
        #pragma unroll
        for (int j=0;j<12;j++) v = fmaf(x0[j], Ws[j*H3+c], v);
        outp[e] = v;
        bsum += v; bsq += v*v;
    }
    atomicAdd(&ssum[c], bsum); atomicAdd(&ssq[c], bsq);
    __syncthreads();
    if (t < H3){ atomicAdd(&g_sum1[t], ssum[t]); atomicAdd(&g_sq1[t], ssq[t]); }
}

template<int C, int LAYER>
__global__ void k_fin(const float* __restrict__ g, const float* __restrict__ be){
    int c = threadIdx.x;
    const float* su = (LAYER==1)? g_sum1 : g_sum2;
    const float* sq = (LAYER==1)? g_sq1  : g_sq2;
    float* bn = (LAYER==1)? g_bn1 : g_bn2;
    float invM = 1.f/(float)MTOT;
    float m = su[c]*invM;
    float v = fmaxf(sq[c]*invM - m*m, 0.f);
    float sc = g[c]*rsqrtf(v+EPSBN);
    bn[c]=sc; bn[C+c]= fmaf(-m, sc, be[c]);
}

// BN+ReLU on the fly, aggregate self + 16 neighbors, /17. float4 per thread.
template<int C, int LAYER>
__global__ __launch_bounds__(256) void k_agg(const int* __restrict__ knn){
    const int TPN = C/4;          // threads per node
    const int NPB = 256/TPN;      // nodes per block
    __shared__ int sidx[NPB][KNB];
    int t = threadIdx.x;
    int n0 = blockIdx.x*NPB;
    if (t < NPB*KNB) sidx[t>>4][t&15] = knn[(size_t)(n0 + (t>>4))*KNB + (t&15)];
    __syncthreads();
    int nl = t / TPN; int c4 = t % TPN;
    int gi = n0 + nl;
    int base = (gi >> 13) * NN;
    const float4* pre = (const float4*)((LAYER==1)? g_pre1 : g_pre2);
    const float*  bn  = (LAYER==1)? g_bn1  : g_bn2;
    float4* agg = (float4*)((LAYER==1)? g_agg1 : g_agg2);
    float4 sc = ((const float4*)bn)[c4];
    float4 sh = ((const float4*)bn)[TPN + c4];
    float4 p = pre[(size_t)gi*TPN + c4];
    float ax = fmaxf(fmaf(p.x, sc.x, sh.x), 0.f);
    float ay = fmaxf(fmaf(p.y, sc.y, sh.y), 0.f);
    float az = fmaxf(fmaf(p.z, sc.z, sh.z), 0.f);
    float aw = fmaxf(fmaf(p.w, sc.w, sh.w), 0.f);
    #pragma unroll
    for (int k=0;k<KNB;k++){
        int nb = base + sidx[nl][k];
        float4 q = pre[(size_t)nb*TPN + c4];
        ax += fmaxf(fmaf(q.x, sc.x, sh.x), 0.f);
        ay += fmaxf(fmaf(q.y, sc.y, sh.y), 0.f);
        az += fmaxf(fmaf(q.z, sc.z, sh.z), 0.f);
        aw += fmaxf(fmaf(q.w, sc.w, sh.w), 0.f);
    }
    const float s = 1.f/17.f;
    agg[(size_t)gi*TPN + c4] = make_float4(ax*s, ay*s, az*s, aw*s);
}

// tiled GEMM: 128 nodes x 128 cols per block, BK=32.
// A stored duplicated (a,a) in smem; W plain. Thread: 8 nodes x (4+4 split) cols.
// A reads are warp-broadcast LDS.128; W reads conflict-free contiguous 128B phases.
// Zero register packing: all FFMA2 operands loaded as 64-bit lanes directly.
template<int CIN, int COUT, bool WOUT, bool MM, int LAYER>
__global__ __launch_bounds__(256) void k_gemm(const float* __restrict__ W, const float* __restrict__ bias){
    const int BK = 32;
    const int ASTR = 260;                        // 256 dup floats + pad (16B aligned rows)
    __shared__ __align__(16) float As2[BK*ASTR];
    __shared__ __align__(16) float Ws[BK*128];
    __shared__ float ssum[128], ssq[128];
    __shared__ uint smx[128], smn[128];
    const float* in = (LAYER==1)? g_agg1 : g_agg2;
    float* sumg = (LAYER==1)? g_sum2 : g_sum3;
    float* sqg  = (LAYER==1)? g_sq2  : g_sq3;
    int t = threadIdx.x;
    int n0 = blockIdx.x*128;
    int cb = blockIdx.y*128;
    int x  = t & 15;            // col group: cols {4x..4x+3} and {64+4x..64+4x+3}
    int cq = x*4;
    int nb = (t >> 4)*8;        // 8 nodes
    if (t < 128){ ssum[t]=0.f; ssq[t]=0.f; if (MM){ smx[t]=0u; smn[t]=0xFFFFFFFFu; } }
    ull acc[8][4];
    #pragma unroll
    for (int n=0;n<8;n++){ acc[n][0]=0ull; acc[n][1]=0ull; acc[n][2]=0ull; acc[n][3]=0ull; }

    // loader indices
    const int fA4 = (t & 7)*4;      // A: float4 along feat
    const int nA  = t >> 3;         // A: node, 32 per pass
    const int cW4 = (t & 31)*4;     // W: float4 along cols
    const int fW  = t >> 5;         // W: row, 8 per pass

    for (int kk=0; kk<CIN; kk+=BK){
        // A tile: 128 nodes x 32 feats -> duplicated pairs
        #pragma unroll
        for (int i=0;i<4;i++){
            int node = nA + 32*i;
            float4 v = *(const float4*)&in[(size_t)(n0 + node)*CIN + kk + fA4];
            *(float2*)&As2[(fA4+0)*ASTR + 2*node] = make_float2(v.x, v.x);
            *(float2*)&As2[(fA4+1)*ASTR + 2*node] = make_float2(v.y, v.y);
            *(float2*)&As2[(fA4+2)*ASTR + 2*node] = make_float2(v.z, v.z);
            *(float2*)&As2[(fA4+3)*ASTR + 2*node] = make_float2(v.w, v.w);
        }
        // W tile: 32 x 128
        #pragma unroll
        for (int i=0;i<4;i++){
            int f = fW + 8*i;
            *(float4*)&Ws[f*128 + cW4] = *(const float4*)&W[(size_t)(kk+f)*COUT + cb + cW4];
        }
        __syncthreads();
        #pragma unroll
        for (int f=0; f<BK; f++){
            ulonglong2 w03 = *(const ulonglong2*)&Ws[f*128 + cq];
            ulonglong2 w47 = *(const ulonglong2*)&Ws[f*128 + 64 + cq];
            const float* Ab = &As2[f*ASTR + 2*nb];
            ulonglong2 a01 = *(const ulonglong2*)(Ab);
            ulonglong2 a23 = *(const ulonglong2*)(Ab + 4);
            ulonglong2 a45 = *(const ulonglong2*)(Ab + 8);
            ulonglong2 a67 = *(const ulonglong2*)(Ab + 12);
            ull av[8] = {a01.x, a01.y, a23.x, a23.y, a45.x, a45.y, a67.x, a67.y};
            #pragma unroll
            for (int n=0;n<8;n++){
                ffma2(acc[n][0], av[n], w03.x);
                ffma2(acc[n][1], av[n], w03.y);
                ffma2(acc[n][2], av[n], w47.x);
                ffma2(acc[n][3], av[n], w47.y);
            }
        }
        __syncthreads();
    }

    // local cols: j=0..3 -> cq+j ; j=4..7 -> 64+cq+(j-4)
    float bv[8], s[8], q[8], mx[8], mn[8];
    #pragma unroll
    for (int j=0;j<8;j++){
        int lc = (j<4)? (cq+j) : (64+cq+j-4);
        bv[j]=bias[cb+lc]; s[j]=0.f; q[j]=0.f; mx[j]=-3.402823466e38f; mn[j]=3.402823466e38f;
    }
    #pragma unroll
    for (int n=0;n<8;n++){
        float v[8];
        #pragma unroll
        for (int h=0;h<4;h++){
            float2 p = unpack2(acc[n][h]);
            v[2*h] = p.x + bv[2*h]; v[2*h+1] = p.y + bv[2*h+1];
        }
        #pragma unroll
        for (int j=0;j<8;j++){
            s[j]+=v[j]; q[j]+=v[j]*v[j];
            if (MM){ mx[j]=fmaxf(mx[j],v[j]); mn[j]=fminf(mn[j],v[j]); }
        }
        if (WOUT){
            *(float4*)(&g_pre2[(size_t)(n0+nb+n)*COUT + cb + cq])      = make_float4(v[0],v[1],v[2],v[3]);
            *(float4*)(&g_pre2[(size_t)(n0+nb+n)*COUT + cb + 64 + cq]) = make_float4(v[4],v[5],v[6],v[7]);
        }
    }
    #pragma unroll
    for (int j=0;j<8;j++){
        int lc = (j<4)? (cq+j) : (64+cq+j-4);
        atomicAdd(&ssum[lc], s[j]); atomicAdd(&ssq[lc], q[j]);
        if (MM){ atomicMax(&smx[lc], fkey(mx[j])); atomicMin(&smn[lc], fkey(mn[j])); }
    }
    __syncthreads();
    if (t < 128){
        atomicAdd(&sumg[cb+t], ssum[t]);
        atomicAdd(&sqg [cb+t], ssq[t]);
        if (MM){
            int b = n0 >> 13;
            atomicMax(&g_maxk[b*H1 + cb + t], smx[t]);
            atomicMin(&g_mink[b*H1 + cb + t], smn[t]);
        }
    }
}

// finalize BN3 + pooled = relu(max over nodes of BN'd value)
__global__ void k_fin3pool(const float* __restrict__ g, const float* __restrict__ be){
    int c = threadIdx.x;
    int b = blockIdx.x;
    float invM = 1.f/(float)MTOT;
    float m = g_sum3[c]*invM;
    float v = fmaxf(g_sq3[c]*invM - m*m, 0.f);
    float sc = g[c]*rsqrtf(v+EPSBN);
    float sh = fmaf(-m, sc, be[c]);
    float mx = keyf(g_maxk[b*H1+c]);
    float mn = keyf(g_mink[b*H1+c]);
    float val = (sc >= 0.f) ? fmaf(mx, sc, sh) : fmaf(mn, sc, sh);
    g_pool[b*H1+c] = fmaxf(val, 0.f);
}

// e2 linear: pre4[b] = pool[b] @ W + bias   (block per batch)
__global__ __launch_bounds__(512) void k_e2(const float* __restrict__ W, const float* __restrict__ bias){
    __shared__ float sp[H1];
    int b = blockIdx.x, c = threadIdx.x;
    sp[c] = g_pool[b*H1 + c];
    __syncthreads();
    float acc = bias[c];
    #pragma unroll 4
    for (int f=0; f<H1; f++) acc = fmaf(sp[f], W[(size_t)f*H1 + c], acc);
    g_pre4[b*H1 + c] = acc;
}

// e2 BN(M=16)+ReLU -> code; decoder per-batch dots; analytic d1 BN params
__global__ __launch_bounds__(512) void k_code2(
    const float* __restrict__ eg, const float* __restrict__ ebe,
    const float* __restrict__ d1w, const float* __restrict__ d1b,
    const float* __restrict__ d1g, const float* __restrict__ d1be,
    const float* __restrict__ d2w, const float* __restrict__ d2b)
{
    __shared__ float scm[BB*H1];
    int t = threadIdx.x;
    float vals[16]; float s = 0.f;
    #pragma unroll
    for (int b=0;b<16;b++){ vals[b]=g_pre4[b*H1+t]; s+=vals[b]; }
    float m = s*(1.f/16.f);
    float q = 0.f;
    #pragma unroll
    for (int b=0;b<16;b++){ float d=vals[b]-m; q+=d*d; }
    float scl = eg[t]*rsqrtf(q*(1.f/16.f)+EPSBN);
    float sh = ebe[t];
    #pragma unroll
    for (int b=0;b<16;b++) scm[b*H1+t] = fmaxf(fmaf(vals[b]-m, scl, sh), 0.f);
    __syncthreads();

    int w = t>>5, lane = t&31;
    if (w < 6){
        for (int d = w*16; d < w*16+16; d++){
            int layer = d/48; int r = d%48; int b = r/3; int c = r%3;
            const float* Wd = layer ? d2w : d1w;
            float p = 0.f;
            for (int f=lane; f<H1; f+=32) p = fmaf(scm[b*H1+f], Wd[f*3+c], p);
            #pragma unroll
            for (int o=16;o;o>>=1) p += __shfl_xor_sync(0xffffffffu, p, o);
            if (lane==0){
                if (layer) g_dc2[b*3+c] = p + d2b[c];
                else       g_dc1[b*3+c] = p + d1b[c];
            }
        }
    }
    __syncthreads();
    if (w < 3){
        float wx = d1w[1536 + w], wy = d1w[1539 + w];
        float sG = 0.f;
        for (int n=lane; n<NN; n+=32){
            int ix = n/65, iy = n - ix*65;
            float gx = 1.f + ix*(119.f/128.f);
            float gy = 1.f + iy*(59.f/64.f);
            sG += gx*wx + gy*wy;
        }
        #pragma unroll
        for (int o=16;o;o>>=1) sG += __shfl_xor_sync(0xffffffffu, sG, o);
        float mG = sG*(1.f/8192.f);
        float qG = 0.f;
        for (int n=lane; n<NN; n+=32){
            int ix = n/65, iy = n - ix*65;
            float gx = 1.f + ix*(119.f/128.f);
            float gy = 1.f + iy*(59.f/64.f);
            float d = gx*wx + gy*wy - mG;
            qG += d*d;
        }
        #pragma unroll
        for (int o=16;o;o>>=1) qG += __shfl_xor_sync(0xffffffffu, qG, o);
        if (lane==0){
            float vG = qG*(1.f/8192.f);
            float sA=0.f;
            #pragma unroll
            for (int b=0;b<16;b++) sA += g_dc1[b*3+w];
            float mA = sA*(1.f/16.f);
            float qA=0.f;
            #pragma unroll
            for (int b=0;b<16;b++){ float d=g_dc1[b*3+w]-mA; qA+=d*d; }
            float vA = qA*(1.f/16.f);
            float mean = mA + mG;
            float var = fmaxf(vA + vG, 0.f);
            float sc1 = d1g[w]*rsqrtf(var+EPSBN);
            g_d1p[w]=sc1; g_d1p[3+w]= d1be[w] - mean*sc1;
        }
    }
}

// per-node decode: z1 (d1+BN+ReLU), z2pre (d2), write z2pre + d2 BN stats
__global__ __launch_bounds__(256) void k_decode(const float* __restrict__ d1w, const float* __restrict__ d2w){
    __shared__ float ss[3], sq_[3];
    int t = threadIdx.x;
    if (t<3){ ss[t]=0.f; sq_[t]=0.f; }
    __syncthreads();
    int gi = blockIdx.x*256 + t;
    int n = gi & (NN-1);
    int b = gi >> 13;
    int ix = n/65, iy = n - ix*65;
    float gx = 1.f + ix*(119.f/128.f);
    float gy = 1.f + iy*(59.f/64.f);
    float z1[3];
    #pragma unroll
    for (int c=0;c<3;c++){
        float pre = g_dc1[b*3+c] + gx*d1w[1536+c] + gy*d1w[1539+c];
        z1[c] = fmaxf(fmaf(pre, g_d1p[c], g_d1p[3+c]), 0.f);
    }
    float v[3];
    #pragma unroll
    for (int c=0;c<3;c++){
        v[c] = g_dc2[b*3+c] + z1[0]*d2w[1536+c] + z1[1]*d2w[1539+c] + z1[2]*d2w[1542+c];
        g_z2[(size_t)gi*3+c] = v[c];
    }
    int lane = t & 31;
    #pragma unroll
    for (int c=0;c<3;c++){
        float sv = v[c], qv = v[c]*v[c];
        #pragma unroll
        for (int o=16;o;o>>=1){ sv += __shfl_xor_sync(0xffffffffu, sv, o); qv += __shfl_xor_sync(0xffffffffu, qv, o); }
        if (lane==0){ atomicAdd(&ss[c], sv); atomicAdd(&sq_[c], qv); }
    }
    __syncthreads();
    if (t<3){ atomicAdd(&g_sumd[t], ss[t]); atomicAdd(&g_sqd[t], sq_[t]); }
}

__global__ void k_out(float* __restrict__ out, const float* __restrict__ g, const float* __restrict__ be){
    int i = blockIdx.x*blockDim.x + threadIdx.x;
    if (i >= MTOT*3) return;
    int c = i % 3;
    float invM = 1.f/(float)MTOT;
    float m = g_sumd[c]*invM;
    float v = fmaxf(g_sqd[c]*invM - m*m, 0.f);
    float sc = g[c]*rsqrtf(v+EPSBN);
    out[i] = fmaxf(fmaf(g_z2[i]-m, sc, be[c]), 0.f);
}

// ---------------- launch ----------------
extern "C" void kernel_launch(void* const* d_in, const int* in_sizes, int n_in,
                              void* d_out, int out_size)
{
    const float* data = (const float*)d_in[0];
    const int*   knn  = (const int*)  d_in[1];
    const float* e1w  = (const float*)d_in[2];
    const float* e1b  = (const float*)d_in[3];
    const float* e1g  = (const float*)d_in[4];
    const float* e1be = (const float*)d_in[5];
    const float* gc1w = (const float*)d_in[6];
    const float* gc1b = (const float*)d_in[7];
    const float* g1g  = (const float*)d_in[8];
    const float* g1be = (const float*)d_in[9];
    const float* gc2w = (const float*)d_in[10];
    const float* gc2b = (const float*)d_in[11];
    const float* g2g  = (const float*)d_in[12];
    const float* g2be = (const float*)d_in[13];
    const float* e2w  = (const float*)d_in[14];
    const float* e2b  = (const float*)d_in[15];
    const float* e2g  = (const float*)d_in[16];
    const float* e2be = (const float*)d_in[17];
    const float* d1w  = (const float*)d_in[18];
    const float* d1b  = (const float*)d_in[19];
    const float* d1g  = (const float*)d_in[20];
    const float* d1be = (const float*)d_in[21];
    const float* d2w  = (const float*)d_in[22];
    const float* d2b  = (const float*)d_in[23];
    const float* d2g  = (const float*)d_in[24];
    const float* d2be = (const float*)d_in[25];
    float* out = (float*)d_out;

    k_zero<<<8, 1024>>>();
    k_cov_e1<<<MTOT/256, 256>>>(data, knn, e1w, e1b);
    k_fin<H3,1><<<1, H3>>>(e1g, e1be);
    k_agg<H3,1><<<MTOT/16, 256>>>(knn);
    k_gemm<H3,H2,true,false,1><<<dim3(MTOT/128,1), 256>>>(gc1w, gc1b);
    k_fin<H2,2><<<1, H2>>>(g1g, g1be);
    k_agg<H2,2><<<MTOT/8, 256>>>(knn);
    k_gemm<H2,H1,false,true,2><<<dim3(MTOT/128,4), 256>>>(gc2w, gc2b);
    k_fin3pool<<<BB, H1>>>(g2g, g2be);
    k_e2<<<BB, H1>>>(e2w, e2b);
    k_code2<<<1, 512>>>(e2g, e2be, d1w, d1b, d1g, d1be, d2w, d2b);
    k_decode<<<MTOT/256, 256>>>(d1w, d2w);
    k_out<<<(MTOT*3+255)/256, 256>>>(out, d2g, d2be);
}

// round 6
// speedup vs baseline: 1.6287x; 1.2891x over previous
#include <cuda_runtime.h>
#include <cuda_bf16.h>
#include <cstdint>

#define BB   16
#define NN   8192
#define KNB  16
#define MTOT (BB*NN)      // 131072
#define H3   64
#define H2   128
#define H1   512
#define EPSBN 1e-5f

typedef unsigned long long ull;
typedef unsigned int uint;

// ---------------- scratch (static device globals; no allocs allowed) ----------------
__device__ float g_pre1[MTOT*H3];
__device__ float g_agg1[MTOT*H3];
__device__ float g_pre2[MTOT*H2];
__device__ uint  g_a2hi[MTOT*64];     // agg2 bf16 hi, 2 ch per u32
__device__ uint  g_a2lo[MTOT*64];     // agg2 bf16 lo
__device__ unsigned short g_w2hi[H1*H2];  // [col][k] bf16 hi of gc2_w^T
__device__ unsigned short g_w2lo[H1*H2];
__device__ float g_z2[MTOT*3];
__device__ float g_sum1[H3], g_sq1[H3];
__device__ float g_sum2[H2], g_sq2[H2];
__device__ float g_sum3[H1], g_sq3[H1];
__device__ uint  g_maxk[BB*H1], g_mink[BB*H1];
__device__ float g_bn1[2*H3];
__device__ float g_bn2[2*H2];
__device__ float g_pool[BB*H1];
__device__ float g_pre4[BB*H1];
__device__ float g_dc1[BB*3], g_dc2[BB*3];
__device__ float g_d1p[6];
__device__ float g_sumd[3], g_sqd[3];

// ---------------- helpers ----------------
__device__ __forceinline__ uint fkey(float f){
    uint u = __float_as_uint(f);
    return (u & 0x80000000u) ? ~u : (u | 0x80000000u);
}
__device__ __forceinline__ float keyf(uint k){
    uint u = (k & 0x80000000u) ? (k ^ 0x80000000u) : ~k;
    return __uint_as_float(u);
}
__device__ __forceinline__ float2 unpack2(ull v){
    float2 f; asm("mov.b64 {%0,%1}, %2;" : "=f"(f.x), "=f"(f.y) : "l"(v)); return f;
}
__device__ __forceinline__ void ffma2(ull &d, ull a, ull b){
    asm("fma.rn.f32x2 %0, %1, %2, %0;" : "+l"(d) : "l"(a), "l"(b));
}
__device__ __forceinline__ uint smem_u32(const void* p){
    uint a; asm("{ .reg .u64 t; cvta.to.shared.u64 t, %1; cvt.u32.u64 %0, t; }" : "=r"(a) : "l"(p)); return a;
}
__device__ __forceinline__ uint pbf2(float a, float b){
    __nv_bfloat162 h = __floats2bfloat162_rn(a, b);
    return *(uint*)&h;
}
__device__ __forceinline__ void ldm4(uint* r, uint addr){
    asm volatile("ldmatrix.sync.aligned.m8n8.x4.shared.b16 {%0,%1,%2,%3}, [%4];"
        : "=r"(r[0]),"=r"(r[1]),"=r"(r[2]),"=r"(r[3]) : "r"(addr));
}
__device__ __forceinline__ void mma16816(float* d, const uint* a, uint b0, uint b1){
    asm volatile("mma.sync.aligned.m16n8k16.row.col.f32.bf16.bf16.f32 "
        "{%0,%1,%2,%3}, {%4,%5,%6,%7}, {%8,%9}, {%0,%1,%2,%3};"
        : "+f"(d[0]),"+f"(d[1]),"+f"(d[2]),"+f"(d[3])
        : "r"(a[0]),"r"(a[1]),"r"(a[2]),"r"(a[3]), "r"(b0),"r"(b1));
}

// ---------------- kernels ----------------
__global__ void k_zero(){
    int i = blockIdx.x*blockDim.x + threadIdx.x;
    if (i < BB*H1){ g_maxk[i]=0u; g_mink[i]=0xFFFFFFFFu; }
    if (i < H1){ g_sum3[i]=0.f; g_sq3[i]=0.f; }
    if (i < H2){ g_sum2[i]=0.f; g_sq2[i]=0.f; }
    if (i < H3){ g_sum1[i]=0.f; g_sq1[i]=0.f; }
    if (i < 3){ g_sumd[i]=0.f; g_sqd[i]=0.f; }
}

// split gc2_w into bf16 hi/lo, transposed to [col][k]
__global__ void k_wsplit(const float* __restrict__ w){
    int i = blockIdx.x*blockDim.x + threadIdx.x;   // i = c*128 + k
    if (i >= H1*H2) return;
    int c = i >> 7, k = i & 127;
    float v = w[(size_t)k*H1 + c];
    __nv_bfloat16 h = __float2bfloat16_rn(v);
    float r = v - __bfloat162float(h);
    __nv_bfloat16 l = __float2bfloat16_rn(r);
    g_w2hi[i] = *(unsigned short*)&h;
    g_w2lo[i] = *(unsigned short*)&l;
}

// covariance features + Linear(12,64) + BN stats
__global__ __launch_bounds__(256) void k_cov_e1(
    const float* __restrict__ data, const int* __restrict__ knn,
    const float* __restrict__ w, const float* __restrict__ bias)
{
    __shared__ float Ws[12*H3];
    __shared__ float bs[H3];
    __shared__ float x0s[256*12];
    __shared__ float ssum[H3], ssq[H3];
    int t = threadIdx.x;
    for (int i = t; i < 12*H3; i += 256) Ws[i] = w[i];
    if (t < H3){ bs[t] = bias[t]; ssum[t]=0.f; ssq[t]=0.f; }

    int gi = blockIdx.x*256 + t;
    int b = gi >> 13;
    const int* kp = knn + (size_t)gi*KNB;
    float sx=0,sy=0,sz=0,sxx=0,sxy=0,sxz=0,syy=0,syz=0,szz=0;
    #pragma unroll
    for (int k=0;k<KNB;k++){
        int j = kp[k];
        const float* p = data + ((size_t)(b*NN + j))*3;
        float x=p[0], y=p[1], z=p[2];
        sx+=x; sy+=y; sz+=z;
        sxx+=x*x; sxy+=x*y; sxz+=x*z; syy+=y*y; syz+=y*z; szz+=z*z;
    }
    float mx=sx*(1.f/16.f), my=sy*(1.f/16.f), mz=sz*(1.f/16.f);
    const float i15 = 1.f/15.f;
    float cxx=(sxx-16.f*mx*mx)*i15, cxy=(sxy-16.f*mx*my)*i15, cxz=(sxz-16.f*mx*mz)*i15;
    float cyy=(syy-16.f*my*my)*i15, cyz=(syz-16.f*my*mz)*i15, czz=(szz-16.f*mz*mz)*i15;
    float* xr = &x0s[t*12];
    xr[0]=data[(size_t)gi*3+0]; xr[1]=data[(size_t)gi*3+1]; xr[2]=data[(size_t)gi*3+2];
    xr[3]=cxx; xr[4]=cxy; xr[5]=cxz; xr[6]=cxy; xr[7]=cyy; xr[8]=cyz; xr[9]=cxz; xr[10]=cyz; xr[11]=czz;
    __syncthreads();

    int c = t & 63;
    float bsum=0.f, bsq=0.f;
    float* outp = g_pre1 + (size_t)blockIdx.x*256*H3;
    #pragma unroll 4
    for (int kq=0;kq<64;kq++){
        int e = t + kq*256;
        const float* x0 = &x0s[(e>>6)*12];
        float v = bs[c];
        #pragma unroll
        for (int j=0;j<12;j++) v = fmaf(x0[j], Ws[j*H3+c], v);
        outp[e] = v;
        bsum += v; bsq += v*v;
    }
    atomicAdd(&ssum[c], bsum); atomicAdd(&ssq[c], bsq);
    __syncthreads();
    if (t < H3){ atomicAdd(&g_sum1[t], ssum[t]); atomicAdd(&g_sq1[t], ssq[t]); }
}

template<int C, int LAYER>
__global__ void k_fin(const float* __restrict__ g, const float* __restrict__ be){
    int c = threadIdx.x;
    const float* su = (LAYER==1)? g_sum1 : g_sum2;
    const float* sq = (LAYER==1)? g_sq1  : g_sq2;
    float* bn = (LAYER==1)? g_bn1 : g_bn2;
    float invM = 1.f/(float)MTOT;
    float m = su[c]*invM;
    float v = fmaxf(sq[c]*invM - m*m, 0.f);
    float sc = g[c]*rsqrtf(v+EPSBN);
    bn[c]=sc; bn[C+c]= fmaf(-m, sc, be[c]);
}

// layer1 agg: BN+ReLU on the fly, self + 16 neighbors, /17, fp32 out
__global__ __launch_bounds__(256) void k_agg1(const int* __restrict__ knn){
    const int TPN = H3/4;         // 16
    const int NPB = 256/TPN;      // 16
    __shared__ int sidx[NPB][KNB];
    int t = threadIdx.x;
    int n0 = blockIdx.x*NPB;
    if (t < NPB*KNB) sidx[t>>4][t&15] = knn[(size_t)(n0 + (t>>4))*KNB + (t&15)];
    __syncthreads();
    int nl = t / TPN; int c4 = t % TPN;
    int gi = n0 + nl;
    int base = (gi >> 13) * NN;
    const float4* pre = (const float4*)g_pre1;
    float4* agg = (float4*)g_agg1;
    float4 sc = ((const float4*)g_bn1)[c4];
    float4 sh = ((const float4*)g_bn1)[TPN + c4];
    float4 p = pre[(size_t)gi*TPN + c4];
    float ax = fmaxf(fmaf(p.x, sc.x, sh.x), 0.f);
    float ay = fmaxf(fmaf(p.y, sc.y, sh.y), 0.f);
    float az = fmaxf(fmaf(p.z, sc.z, sh.z), 0.f);
    float aw = fmaxf(fmaf(p.w, sc.w, sh.w), 0.f);
    #pragma unroll
    for (int k=0;k<KNB;k++){
        int nb = base + sidx[nl][k];
        float4 q = pre[(size_t)nb*TPN + c4];
        ax += fmaxf(fmaf(q.x, sc.x, sh.x), 0.f);
        ay += fmaxf(fmaf(q.y, sc.y, sh.y), 0.f);
        az += fmaxf(fmaf(q.z, sc.z, sh.z), 0.f);
        aw += fmaxf(fmaf(q.w, sc.w, sh.w), 0.f);
    }
    const float s = 1.f/17.f;
    agg[(size_t)gi*TPN + c4] = make_float4(ax*s, ay*s, az*s, aw*s);
}

// layer2 agg: same math but emits bf16 hi/lo split for mma gemm2
__global__ __launch_bounds__(256) void k_agg2(const int* __restrict__ knn){
    const int TPN = H2/4;         // 32
    const int NPB = 256/TPN;      // 8
    __shared__ int sidx[NPB][KNB];
    int t = threadIdx.x;
    int n0 = blockIdx.x*NPB;
    if (t < NPB*KNB) sidx[t>>4][t&15] = knn[(size_t)(n0 + (t>>4))*KNB + (t&15)];
    __syncthreads();
    int nl = t / TPN; int c4 = t % TPN;
    int gi = n0 + nl;
    int base = (gi >> 13) * NN;
    const float4* pre = (const float4*)g_pre2;
    float4 sc = ((const float4*)g_bn2)[c4];
    float4 sh = ((const float4*)g_bn2)[TPN + c4];
    float4 p = pre[(size_t)gi*TPN + c4];
    float ax = fmaxf(fmaf(p.x, sc.x, sh.x), 0.f);
    float ay = fmaxf(fmaf(p.y, sc.y, sh.y), 0.f);
    float az = fmaxf(fmaf(p.z, sc.z, sh.z), 0.f);
    float aw = fmaxf(fmaf(p.w, sc.w, sh.w), 0.f);
    #pragma unroll
    for (int k=0;k<KNB;k++){
        int nb = base + sidx[nl][k];
        float4 q = pre[(size_t)nb*TPN + c4];
        ax += fmaxf(fmaf(q.x, sc.x, sh.x), 0.f);
        ay += fmaxf(fmaf(q.y, sc.y, sh.y), 0.f);
        az += fmaxf(fmaf(q.z, sc.z, sh.z), 0.f);
        aw += fmaxf(fmaf(q.w, sc.w, sh.w), 0.f);
    }
    const float s = 1.f/17.f;
    ax*=s; ay*=s; az*=s; aw*=s;
    __nv_bfloat162 h01 = __floats2bfloat162_rn(ax, ay);
    __nv_bfloat162 h23 = __floats2bfloat162_rn(az, aw);
    float rx = ax - __bfloat162float(h01.x);
    float ry = ay - __bfloat162float(h01.y);
    float rz = az - __bfloat162float(h23.x);
    float rw = aw - __bfloat162float(h23.y);
    size_t o = (size_t)gi*64 + c4*2;
    g_a2hi[o]   = *(uint*)&h01;
    g_a2hi[o+1] = *(uint*)&h23;
    g_a2lo[o]   = pbf2(rx, ry);
    g_a2lo[o+1] = pbf2(rz, rw);
}

// gemm1: 128 nodes x 128 cols per block, BK=32, dup-A f32x2
__global__ __launch_bounds__(256) void k_gemm1(const float* __restrict__ W, const float* __restrict__ bias){
    const int BK = 32;
    const int CIN = H3, COUT = H2;
    const int ASTR = 260;
    __shared__ __align__(16) float As2[BK*ASTR];
    __shared__ __align__(16) float Ws[BK*128];
    __shared__ float ssum[128], ssq[128];
    int t = threadIdx.x;
    int n0 = blockIdx.x*128;
    int x  = t & 15;
    int cq = x*4;
    int nb = (t >> 4)*8;
    if (t < 128){ ssum[t]=0.f; ssq[t]=0.f; }
    ull acc[8][4];
    #pragma unroll
    for (int n=0;n<8;n++){ acc[n][0]=0ull; acc[n][1]=0ull; acc[n][2]=0ull; acc[n][3]=0ull; }

    const int fA4 = (t & 7)*4;
    const int nA  = t >> 3;
    const int cW4 = (t & 31)*4;
    const int fW  = t >> 5;

    for (int kk=0; kk<CIN; kk+=BK){
        #pragma unroll
        for (int i=0;i<4;i++){
            int node = nA + 32*i;
            float4 v = *(const float4*)&g_agg1[(size_t)(n0 + node)*CIN + kk + fA4];
            *(float2*)&As2[(fA4+0)*ASTR + 2*node] = make_float2(v.x, v.x);
            *(float2*)&As2[(fA4+1)*ASTR + 2*node] = make_float2(v.y, v.y);
            *(float2*)&As2[(fA4+2)*ASTR + 2*node] = make_float2(v.z, v.z);
            *(float2*)&As2[(fA4+3)*ASTR + 2*node] = make_float2(v.w, v.w);
        }
        #pragma unroll
        for (int i=0;i<4;i++){
            int f = fW + 8*i;
            *(float4*)&Ws[f*128 + cW4] = *(const float4*)&W[(size_t)(kk+f)*COUT + cW4];
        }
        __syncthreads();
        #pragma unroll
        for (int f=0; f<BK; f++){
            ulonglong2 w03 = *(const ulonglong2*)&Ws[f*128 + cq];
            ulonglong2 w47 = *(const ulonglong2*)&Ws[f*128 + 64 + cq];
            const float* Ab = &As2[f*ASTR + 2*nb];
            ulonglong2 a01 = *(const ulonglong2*)(Ab);
            ulonglong2 a23 = *(const ulonglong2*)(Ab + 4);
            ulonglong2 a45 = *(const ulonglong2*)(Ab + 8);
            ulonglong2 a67 = *(const ulonglong2*)(Ab + 12);
            ull av[8] = {a01.x, a01.y, a23.x, a23.y, a45.x, a45.y, a67.x, a67.y};
            #pragma unroll
            for (int n=0;n<8;n++){
                ffma2(acc[n][0], av[n], w03.x);
                ffma2(acc[n][1], av[n], w03.y);
                ffma2(acc[n][2], av[n], w47.x);
                ffma2(acc[n][3], av[n], w47.y);
            }
        }
        __syncthreads();
    }

    float bv[8], s[8], q[8];
    #pragma unroll
    for (int j=0;j<8;j++){
        int lc = (j<4)? (cq+j) : (64+cq+j-4);
        bv[j]=bias[lc]; s[j]=0.f; q[j]=0.f;
    }
    #pragma unroll
    for (int n=0;n<8;n++){
        float v[8];
        #pragma unroll
        for (int h=0;h<4;h++){
            float2 p = unpack2(acc[n][h]);
            v[2*h] = p.x + bv[2*h]; v[2*h+1] = p.y + bv[2*h+1];
        }
        #pragma unroll
        for (int j=0;j<8;j++){ s[j]+=v[j]; q[j]+=v[j]*v[j]; }
        *(float4*)(&g_pre2[(size_t)(n0+nb+n)*COUT + cq])      = make_float4(v[0],v[1],v[2],v[3]);
        *(float4*)(&g_pre2[(size_t)(n0+nb+n)*COUT + 64 + cq]) = make_float4(v[4],v[5],v[6],v[7]);
    }
    #pragma unroll
    for (int j=0;j<8;j++){
        int lc = (j<4)? (cq+j) : (64+cq+j-4);
        atomicAdd(&ssum[lc], s[j]); atomicAdd(&ssq[lc], q[j]);
    }
    __syncthreads();
    if (t < 128){
        atomicAdd(&g_sum2[t], ssum[t]);
        atomicAdd(&g_sq2[t], ssq[t]);
    }
}

// ---------------- gemm2: legacy mma.sync bf16 split-precision ----------------
// CTA = 128 nodes x 512 cols (4 quarters sequentially), K=128 in smem.
// A read once; per quarter load B; accumulate only stats (no D writeback).
#define AH_OFF 0u
#define AL_OFF 34816u
#define BH_OFF 69632u
#define BL_OFF 104448u
#define SSUM_OFF 139264u
#define SSQ_OFF  139776u
#define SMX_OFF  140288u
#define SMN_OFF  140800u
#define G2_SMEM  141312

__global__ void __launch_bounds__(256) k_gemm2_mma(){
    extern __shared__ __align__(16) char sm[];
    uint sb = smem_u32(sm);
    int t = threadIdx.x, lane = t & 31, wid = t >> 5;
    int wm = wid >> 2, wn = wid & 3;
    int node0 = blockIdx.x*128;
    int batch = blockIdx.x >> 6;

    float* ssum = (float*)(sm + SSUM_OFF);
    float* ssq  = (float*)(sm + SSQ_OFF);
    uint*  smx  = (uint*)(sm + SMX_OFF);
    uint*  smn  = (uint*)(sm + SMN_OFF);

    // load A hi/lo (128 rows x 128 bf16 = 256B/row, padded stride 272B)
    {
        int row = t >> 1, half = t & 1;
        const uint4* ph = (const uint4*)(g_a2hi + (size_t)(node0+row)*64) + half*8;
        const uint4* pl = (const uint4*)(g_a2lo + (size_t)(node0+row)*64) + half*8;
        uint4* dh = (uint4*)(sm + AH_OFF + row*272 + half*128);
        uint4* dl = (uint4*)(sm + AL_OFF + row*272 + half*128);
        #pragma unroll
        for (int i=0;i<8;i++){ dh[i] = ph[i]; dl[i] = pl[i]; }
    }

    // ldmatrix base addresses
    uint aBase = sb + AH_OFF + (uint)((wm*64 + (lane & 15))*272 + (lane >> 4)*16);
    uint bBase = sb + BH_OFF + (uint)((wn*32 + (lane & 7) + ((lane >> 4) & 1)*8)*272 + ((lane >> 3) & 1)*16);

    for (int q = 0; q < 4; q++){
        int cb = q*128;
        // load B quarter (128 cols x 128 k = 256B/col-row, hi/lo)
        {
            int col = t >> 1, half = t & 1;
            const uint4* ph = (const uint4*)((const char*)g_w2hi + (size_t)(cb+col)*256) + half*8;
            const uint4* pl = (const uint4*)((const char*)g_w2lo + (size_t)(cb+col)*256) + half*8;
            uint4* dh = (uint4*)(sm + BH_OFF + col*272 + half*128);
            uint4* dl = (uint4*)(sm + BL_OFF + col*272 + half*128);
            #pragma unroll
            for (int i=0;i<8;i++){ dh[i] = ph[i]; dl[i] = pl[i]; }
        }
        if (t < 128){ ssum[t]=0.f; ssq[t]=0.f; smx[t]=0u; smn[t]=0xFFFFFFFFu; }
        __syncthreads();

        float acc[4][4][4];
        #pragma unroll
        for (int mi=0;mi<4;mi++)
            #pragma unroll
            for (int j=0;j<4;j++)
                #pragma unroll
                for (int r=0;r<4;r++) acc[mi][j][r] = 0.f;

        #pragma unroll
        for (int ks=0; ks<8; ks++){
            uint bh[8], bl[8];
            ldm4(bh,   bBase + ks*32);
            ldm4(bh+4, bBase + 16*272 + ks*32);
            ldm4(bl,   bBase + (BL_OFF-BH_OFF) + ks*32);
            ldm4(bl+4, bBase + (BL_OFF-BH_OFF) + 16*272 + ks*32);
            #pragma unroll
            for (int mi=0; mi<4; mi++){
                uint ah[4], al[4];
                ldm4(ah, aBase + mi*16*272 + ks*32);
                ldm4(al, aBase + (AL_OFF-AH_OFF) + mi*16*272 + ks*32);
                #pragma unroll
                for (int j=0;j<4;j++){
                    mma16816(acc[mi][j], ah, bh[2*j], bh[2*j+1]);
                    mma16816(acc[mi][j], al, bh[2*j], bh[2*j+1]);
                    mma16816(acc[mi][j], ah, bl[2*j], bl[2*j+1]);
                }
            }
        }

        // epilogue: per-column stats (raw, bias folded in later)
        #pragma unroll
        for (int j=0;j<4;j++){
            #pragma unroll
            for (int p=0;p<2;p++){
                float s=0.f, qq=0.f, mx=-3.402823466e38f, mn=3.402823466e38f;
                #pragma unroll
                for (int mi=0;mi<4;mi++){
                    #pragma unroll
                    for (int r=0;r<2;r++){
                        float v = acc[mi][j][2*r+p];
                        s += v; qq = fmaf(v, v, qq);
                        mx = fmaxf(mx, v); mn = fminf(mn, v);
                    }
                }
                #pragma unroll
                for (int o=4;o<32;o<<=1){
                    s  += __shfl_xor_sync(0xffffffffu, s, o);
                    qq += __shfl_xor_sync(0xffffffffu, qq, o);
                    mx = fmaxf(mx, __shfl_xor_sync(0xffffffffu, mx, o));
                    mn = fminf(mn, __shfl_xor_sync(0xffffffffu, mn, o));
                }
                if (lane < 4){
                    int colq = wn*32 + j*8 + lane*2 + p;
                    atomicAdd(&ssum[colq], s);
                    atomicAdd(&ssq[colq], qq);
                    atomicMax(&smx[colq], fkey(mx));
                    atomicMin(&smn[colq], fkey(mn));
                }
            }
        }
        __syncthreads();
        if (t < 128){
            atomicAdd(&g_sum3[cb+t], ssum[t]);
            atomicAdd(&g_sq3[cb+t], ssq[t]);
            atomicMax(&g_maxk[batch*H1 + cb + t], smx[t]);
            atomicMin(&g_mink[batch*H1 + cb + t], smn[t]);
        }
        __syncthreads();
    }
}

// finalize BN3 + pooled; stats were accumulated WITHOUT gc2 bias (fold it here)
__global__ void k_fin3pool(const float* __restrict__ g, const float* __restrict__ be,
                           const float* __restrict__ bias){
    int c = threadIdx.x;
    int b = blockIdx.x;
    float invM = 1.f/(float)MTOT;
    float bi = bias[c];
    float s = g_sum3[c]*invM;          // raw mean
    float q = g_sq3[c]*invM;           // raw E[x^2]
    float m = s + bi;                  // true mean (shift)
    float v = fmaxf(q - s*s, 0.f);     // variance is shift-invariant
    float sc = g[c]*rsqrtf(v+EPSBN);
    float sh = fmaf(-m, sc, be[c]);
    float mx = keyf(g_maxk[b*H1+c]) + bi;
    float mn = keyf(g_mink[b*H1+c]) + bi;
    float val = (sc >= 0.f) ? fmaf(mx, sc, sh) : fmaf(mn, sc, sh);
    g_pool[b*H1+c] = fmaxf(val, 0.f);
}

// e2 linear: pre4[b] = pool[b] @ W + bias   (block per batch)
__global__ __launch_bounds__(512) void k_e2(const float* __restrict__ W, const float* __restrict__ bias){
    __shared__ float sp[H1];
    int b = blockIdx.x, c = threadIdx.x;
    sp[c] = g_pool[b*H1 + c];
    __syncthreads();
    float acc = bias[c];
    #pragma unroll 4
    for (int f=0; f<H1; f++) acc = fmaf(sp[f], W[(size_t)f*H1 + c], acc);
    g_pre4[b*H1 + c] = acc;
}

// e2 BN(M=16)+ReLU -> code; decoder per-batch dots; analytic d1 BN params
__global__ __launch_bounds__(512) void k_code2(
    const float* __restrict__ eg, const float* __restrict__ ebe,
    const float* __restrict__ d1w, const float* __restrict__ d1b,
    const float* __restrict__ d1g, const float* __restrict__ d1be,
    const float* __restrict__ d2w, const float* __restrict__ d2b)
{
    __shared__ float scm[BB*H1];
    int t = threadIdx.x;
    float vals[16]; float s = 0.f;
    #pragma unroll
    for (int b=0;b<16;b++){ vals[b]=g_pre4[b*H1+t]; s+=vals[b]; }
    float m = s*(1.f/16.f);
    float q = 0.f;
    #pragma unroll
    for (int b=0;b<16;b++){ float d=vals[b]-m; q+=d*d; }
    float scl = eg[t]*rsqrtf(q*(1.f/16.f)+EPSBN);
    float sh = ebe[t];
    #pragma unroll
    for (int b=0;b<16;b++) scm[b*H1+t] = fmaxf(fmaf(vals[b]-m, scl, sh), 0.f);
    __syncthreads();

    int w = t>>5, lane = t&31;
    if (w < 6){
        for (int d = w*16; d < w*16+16; d++){
            int layer = d/48; int r = d%48; int b = r/3; int c = r%3;
            const float* Wd = layer ? d2w : d1w;
            float p = 0.f;
            for (int f=lane; f<H1; f+=32) p = fmaf(scm[b*H1+f], Wd[f*3+c], p);
            #pragma unroll
            for (int o=16;o;o>>=1) p += __shfl_xor_sync(0xffffffffu, p, o);
            if (lane==0){
                if (layer) g_dc2[b*3+c] = p + d2b[c];
                else       g_dc1[b*3+c] = p + d1b[c];
            }
        }
    }
    __syncthreads();
    if (w < 3){
        float wx = d1w[1536 + w], wy = d1w[1539 + w];
        float sG = 0.f;
        for (int n=lane; n<NN; n+=32){
            int ix = n/65, iy = n - ix*65;
            float gx = 1.f + ix*(119.f/128.f);
            float gy = 1.f + iy*(59.f/64.f);
            sG += gx*wx + gy*wy;
        }
        #pragma unroll
        for (int o=16;o;o>>=1) sG += __shfl_xor_sync(0xffffffffu, sG, o);
        float mG = sG*(1.f/8192.f);
        float qG = 0.f;
        for (int n=lane; n<NN; n+=32){
            int ix = n/65, iy = n - ix*65;
            float gx = 1.f + ix*(119.f/128.f);
            float gy = 1.f + iy*(59.f/64.f);
            float d = gx*wx + gy*wy - mG;
            qG += d*d;
        }
        #pragma unroll
        for (int o=16;o;o>>=1) qG += __shfl_xor_sync(0xffffffffu, qG, o);
        if (lane==0){
            float vG = qG*(1.f/8192.f);
            float sA=0.f;
            #pragma unroll
            for (int b=0;b<16;b++) sA += g_dc1[b*3+w];
            float mA = sA*(1.f/16.f);
            float qA=0.f;
            #pragma unroll
            for (int b=0;b<16;b++){ float d=g_dc1[b*3+w]-mA; qA+=d*d; }
            float vA = qA*(1.f/16.f);
            float mean = mA + mG;
            float var = fmaxf(vA + vG, 0.f);
            float sc1 = d1g[w]*rsqrtf(var+EPSBN);
            g_d1p[w]=sc1; g_d1p[3+w]= d1be[w] - mean*sc1;
        }
    }
}

// per-node decode: z1 (d1+BN+ReLU), z2pre (d2), write z2pre + d2 BN stats
__global__ __launch_bounds__(256) void k_decode(const float* __restrict__ d1w, const float* __restrict__ d2w){
    __shared__ float ss[3], sq_[3];
    int t = threadIdx.x;
    if (t<3){ ss[t]=0.f; sq_[t]=0.f; }
    __syncthreads();
    int gi = blockIdx.x*256 + t;
    int n = gi & (NN-1);
    int b = gi >> 13;
    int ix = n/65, iy = n - ix*65;
    float gx = 1.f + ix*(119.f/128.f);
    float gy = 1.f + iy*(59.f/64.f);
    float z1[3];
    #pragma unroll
    for (int c=0;c<3;c++){
        float pre = g_dc1[b*3+c] + gx*d1w[1536+c] + gy*d1w[1539+c];
        z1[c] = fmaxf(fmaf(pre, g_d1p[c], g_d1p[3+c]), 0.f);
    }
    float v[3];
    #pragma unroll
    for (int c=0;c<3;c++){
        v[c] = g_dc2[b*3+c] + z1[0]*d2w[1536+c] + z1[1]*d2w[1539+c] + z1[2]*d2w[1542+c];
        g_z2[(size_t)gi*3+c] = v[c];
    }
    int lane = t & 31;
    #pragma unroll
    for (int c=0;c<3;c++){
        float sv = v[c], qv = v[c]*v[c];
        #pragma unroll
        for (int o=16;o;o>>=1){ sv += __shfl_xor_sync(0xffffffffu, sv, o); qv += __shfl_xor_sync(0xffffffffu, qv, o); }
        if (lane==0){ atomicAdd(&ss[c], sv); atomicAdd(&sq_[c], qv); }
    }
    __syncthreads();
    if (t<3){ atomicAdd(&g_sumd[t], ss[t]); atomicAdd(&g_sqd[t], sq_[t]); }
}

__global__ void k_out(float* __restrict__ out, const float* __restrict__ g, const float* __restrict__ be){
    int i = blockIdx.x*blockDim.x + threadIdx.x;
    if (i >= MTOT*3) return;
    int c = i % 3;
    float invM = 1.f/(float)MTOT;
    float m = g_sumd[c]*invM;
    float v = fmaxf(g_sqd[c]*invM - m*m, 0.f);
    float sc = g[c]*rsqrtf(v+EPSBN);
    out[i] = fmaxf(fmaf(g_z2[i]-m, sc, be[c]), 0.f);
}

// ---------------- launch ----------------
extern "C" void kernel_launch(void* const* d_in, const int* in_sizes, int n_in,
                              void* d_out, int out_size)
{
    const float* data = (const float*)d_in[0];
    const int*   knn  = (const int*)  d_in[1];
    const float* e1w  = (const float*)d_in[2];
    const float* e1b  = (const float*)d_in[3];
    const float* e1g  = (const float*)d_in[4];
    const float* e1be = (const float*)d_in[5];
    const float* gc1w = (const float*)d_in[6];
    const float* gc1b = (const float*)d_in[7];
    const float* g1g  = (const float*)d_in[8];
    const float* g1be = (const float*)d_in[9];
    const float* gc2w = (const float*)d_in[10];
    const float* gc2b = (const float*)d_in[11];
    const float* g2g  = (const float*)d_in[12];
    const float* g2be = (const float*)d_in[13];
    const float* e2w  = (const float*)d_in[14];
    const float* e2b  = (const float*)d_in[15];
    const float* e2g  = (const float*)d_in[16];
    const float* e2be = (const float*)d_in[17];
    const float* d1w  = (const float*)d_in[18];
    const float* d1b  = (const float*)d_in[19];
    const float* d1g  = (const float*)d_in[20];
    const float* d1be = (const float*)d_in[21];
    const float* d2w  = (const float*)d_in[22];
    const float* d2b  = (const float*)d_in[23];
    const float* d2g  = (const float*)d_in[24];
    const float* d2be = (const float*)d_in[25];
    float* out = (float*)d_out;

    cudaFuncSetAttribute(k_gemm2_mma, cudaFuncAttributeMaxDynamicSharedMemorySize, G2_SMEM);

    k_zero<<<8, 1024>>>();
    k_wsplit<<<(H1*H2+255)/256, 256>>>(gc2w);
    k_cov_e1<<<MTOT/256, 256>>>(data, knn, e1w, e1b);
    k_fin<H3,1><<<1, H3>>>(e1g, e1be);
    k_agg1<<<MTOT/16, 256>>>(knn);
    k_gemm1<<<MTOT/128, 256>>>(gc1w, gc1b);
    k_fin<H2,2><<<1, H2>>>(g1g, g1be);
    k_agg2<<<MTOT/8, 256>>>(knn);
    k_gemm2_mma<<<MTOT/128, 256, G2_SMEM>>>();
    k_fin3pool<<<BB, H1>>>(g2g, g2be, gc2b);
    k_e2<<<BB, H1>>>(e2w, e2b);
    k_code2<<<1, 512>>>(e2g, e2be, d1w, d1b, d1g, d1be, d2w, d2b);
    k_decode<<<MTOT/256, 256>>>(d1w, d2w);
    k_out<<<(MTOT*3+255)/256, 256>>>(out, d2g, d2be);
}

// round 7
// speedup vs baseline: 1.7211x; 1.0568x over previous
#include <cuda_runtime.h>
#include <cuda_bf16.h>
#include <cstdint>

#define BB   16
#define NN   8192
#define KNB  16
#define MTOT (BB*NN)      // 131072
#define H3   64
#define H2   128
#define H1   512
#define EPSBN 1e-5f

typedef unsigned long long ull;
typedef unsigned int uint;

// ---------------- scratch ----------------
__device__ float g_pre1[MTOT*H3];
__device__ uint  g_a1hi[MTOT*32];     // agg1 bf16 hi (64ch -> 32 u32)
__device__ uint  g_a1lo[MTOT*32];
__device__ float g_pre2[MTOT*H2];
__device__ uint  g_a2hi[MTOT*64];     // agg2 bf16 hi (128ch -> 64 u32)
__device__ uint  g_a2lo[MTOT*64];
__device__ unsigned short g_w1hi[H2*H3];  // [col][k] bf16 hi of gc1_w^T (128x64)
__device__ unsigned short g_w1lo[H2*H3];
__device__ unsigned short g_w2hi[H1*H2];  // [col][k] bf16 hi of gc2_w^T (512x128)
__device__ unsigned short g_w2lo[H1*H2];
__device__ float g_z2[MTOT*3];
__device__ float g_sum1[H3], g_sq1[H3];
__device__ float g_sum2[H2], g_sq2[H2];
__device__ float g_sum3[H1], g_sq3[H1];
__device__ uint  g_maxk[BB*H1], g_mink[BB*H1];
__device__ float g_bn1[2*H3];
__device__ float g_bn2[2*H2];
__device__ float g_pool[BB*H1];
__device__ float g_pre4[BB*H1];
__device__ float g_dc1[BB*3], g_dc2[BB*3];
__device__ float g_d1p[6];
__device__ float g_sumd[3], g_sqd[3];

// ---------------- helpers ----------------
__device__ __forceinline__ uint fkey(float f){
    uint u = __float_as_uint(f);
    return (u & 0x80000000u) ? ~u : (u | 0x80000000u);
}
__device__ __forceinline__ float keyf(uint k){
    uint u = (k & 0x80000000u) ? (k ^ 0x80000000u) : ~k;
    return __uint_as_float(u);
}
__device__ __forceinline__ uint smem_u32(const void* p){
    uint a; asm("{ .reg .u64 t; cvta.to.shared.u64 t, %1; cvt.u32.u64 %0, t; }" : "=r"(a) : "l"(p)); return a;
}
__device__ __forceinline__ uint pbf2(float a, float b){
    __nv_bfloat162 h = __floats2bfloat162_rn(a, b);
    return *(uint*)&h;
}
__device__ __forceinline__ void ldm4(uint* r, uint addr){
    asm volatile("ldmatrix.sync.aligned.m8n8.x4.shared.b16 {%0,%1,%2,%3}, [%4];"
        : "=r"(r[0]),"=r"(r[1]),"=r"(r[2]),"=r"(r[3]) : "r"(addr));
}
__device__ __forceinline__ void mma16816(float* d, const uint* a, uint b0, uint b1){
    asm volatile("mma.sync.aligned.m16n8k16.row.col.f32.bf16.bf16.f32 "
        "{%0,%1,%2,%3}, {%4,%5,%6,%7}, {%8,%9}, {%0,%1,%2,%3};"
        : "+f"(d[0]),"+f"(d[1]),"+f"(d[2]),"+f"(d[3])
        : "r"(a[0]),"r"(a[1]),"r"(a[2]),"r"(a[3]), "r"(b0),"r"(b1));
}

// ---------------- init: zero stats + split both weight matrices ----------------
__global__ void k_init(const float* __restrict__ w1, const float* __restrict__ w2){
    int i = blockIdx.x*blockDim.x + threadIdx.x;   // 0..65535
    if (i < H1*H2){  // gc2w split: i = c*128 + k
        int c = i >> 7, k = i & 127;
        float v = w2[(size_t)k*H1 + c];
        __nv_bfloat16 h = __float2bfloat16_rn(v);
        float r = v - __bfloat162float(h);
        __nv_bfloat16 l = __float2bfloat16_rn(r);
        g_w2hi[i] = *(unsigned short*)&h;
        g_w2lo[i] = *(unsigned short*)&l;
    }
    if (i < H2*H3){  // gc1w split: i = c*64 + k
        int c = i >> 6, k = i & 63;
        float v = w1[(size_t)k*H2 + c];
        __nv_bfloat16 h = __float2bfloat16_rn(v);
        float r = v - __bfloat162float(h);
        __nv_bfloat16 l = __float2bfloat16_rn(r);
        g_w1hi[i] = *(unsigned short*)&h;
        g_w1lo[i] = *(unsigned short*)&l;
    }
    if (i < BB*H1){ g_maxk[i]=0u; g_mink[i]=0xFFFFFFFFu; }
    if (i < H1){ g_sum3[i]=0.f; g_sq3[i]=0.f; }
    if (i < H2){ g_sum2[i]=0.f; g_sq2[i]=0.f; }
    if (i < H3){ g_sum1[i]=0.f; g_sq1[i]=0.f; }
    if (i < 3){ g_sumd[i]=0.f; g_sqd[i]=0.f; }
}

// covariance features + Linear(12,64) + BN stats
__global__ __launch_bounds__(256) void k_cov_e1(
    const float* __restrict__ data, const int* __restrict__ knn,
    const float* __restrict__ w, const float* __restrict__ bias)
{
    __shared__ float Ws[12*H3];
    __shared__ float bs[H3];
    __shared__ float x0s[256*12];
    __shared__ float ssum[H3], ssq[H3];
    int t = threadIdx.x;
    for (int i = t; i < 12*H3; i += 256) Ws[i] = w[i];
    if (t < H3){ bs[t] = bias[t]; ssum[t]=0.f; ssq[t]=0.f; }

    int gi = blockIdx.x*256 + t;
    int b = gi >> 13;
    const int* kp = knn + (size_t)gi*KNB;
    float sx=0,sy=0,sz=0,sxx=0,sxy=0,sxz=0,syy=0,syz=0,szz=0;
    #pragma unroll
    for (int k=0;k<KNB;k++){
        int j = kp[k];
        const float* p = data + ((size_t)(b*NN + j))*3;
        float x=p[0], y=p[1], z=p[2];
        sx+=x; sy+=y; sz+=z;
        sxx+=x*x; sxy+=x*y; sxz+=x*z; syy+=y*y; syz+=y*z; szz+=z*z;
    }
    float mx=sx*(1.f/16.f), my=sy*(1.f/16.f), mz=sz*(1.f/16.f);
    const float i15 = 1.f/15.f;
    float cxx=(sxx-16.f*mx*mx)*i15, cxy=(sxy-16.f*mx*my)*i15, cxz=(sxz-16.f*mx*mz)*i15;
    float cyy=(syy-16.f*my*my)*i15, cyz=(syz-16.f*my*mz)*i15, czz=(szz-16.f*mz*mz)*i15;
    float* xr = &x0s[t*12];
    xr[0]=data[(size_t)gi*3+0]; xr[1]=data[(size_t)gi*3+1]; xr[2]=data[(size_t)gi*3+2];
    xr[3]=cxx; xr[4]=cxy; xr[5]=cxz; xr[6]=cxy; xr[7]=cyy; xr[8]=cyz; xr[9]=cxz; xr[10]=cyz; xr[11]=czz;
    __syncthreads();

    int c = t & 63;
    float bsum=0.f, bsq=0.f;
    float* outp = g_pre1 + (size_t)blockIdx.x*256*H3;
    #pragma unroll 4
    for (int kq=0;kq<64;kq++){
        int e = t + kq*256;
        const float* x0 = &x0s[(e>>6)*12];
        float v = bs[c];
        #pragma unroll
        for (int j=0;j<12;j++) v = fmaf(x0[j], Ws[j*H3+c], v);
        outp[e] = v;
        bsum += v; bsq += v*v;
    }
    atomicAdd(&ssum[c], bsum); atomicAdd(&ssq[c], bsq);
    __syncthreads();
    if (t < H3){ atomicAdd(&g_sum1[t], ssum[t]); atomicAdd(&g_sq1[t], ssq[t]); }
}

template<int C, int LAYER>
__global__ void k_fin(const float* __restrict__ g, const float* __restrict__ be){
    int c = threadIdx.x;
    const float* su = (LAYER==1)? g_sum1 : g_sum2;
    const float* sq = (LAYER==1)? g_sq1  : g_sq2;
    float* bn = (LAYER==1)? g_bn1 : g_bn2;
    float invM = 1.f/(float)MTOT;
    float m = su[c]*invM;
    float v = fmaxf(sq[c]*invM - m*m, 0.f);
    float sc = g[c]*rsqrtf(v+EPSBN);
    bn[c]=sc; bn[C+c]= fmaf(-m, sc, be[c]);
}

// layer1 agg: BN+ReLU on the fly, self + 16 neighbors, /17 -> bf16 hi/lo
__global__ __launch_bounds__(256) void k_agg1(const int* __restrict__ knn){
    const int TPN = H3/4;         // 16
    const int NPB = 256/TPN;      // 16
    __shared__ int sidx[NPB][KNB];
    int t = threadIdx.x;
    int n0 = blockIdx.x*NPB;
    if (t < NPB*KNB) sidx[t>>4][t&15] = knn[(size_t)(n0 + (t>>4))*KNB + (t&15)];
    __syncthreads();
    int nl = t / TPN; int c4 = t % TPN;
    int gi = n0 + nl;
    int base = (gi >> 13) * NN;
    const float4* pre = (const float4*)g_pre1;
    float4 sc = ((const float4*)g_bn1)[c4];
    float4 sh = ((const float4*)g_bn1)[TPN + c4];
    float4 p = pre[(size_t)gi*TPN + c4];
    float ax = fmaxf(fmaf(p.x, sc.x, sh.x), 0.f);
    float ay = fmaxf(fmaf(p.y, sc.y, sh.y), 0.f);
    float az = fmaxf(fmaf(p.z, sc.z, sh.z), 0.f);
    float aw = fmaxf(fmaf(p.w, sc.w, sh.w), 0.f);
    #pragma unroll
    for (int k=0;k<KNB;k++){
        int nb = base + sidx[nl][k];
        float4 q = pre[(size_t)nb*TPN + c4];
        ax += fmaxf(fmaf(q.x, sc.x, sh.x), 0.f);
        ay += fmaxf(fmaf(q.y, sc.y, sh.y), 0.f);
        az += fmaxf(fmaf(q.z, sc.z, sh.z), 0.f);
        aw += fmaxf(fmaf(q.w, sc.w, sh.w), 0.f);
    }
    const float s = 1.f/17.f;
    ax*=s; ay*=s; az*=s; aw*=s;
    __nv_bfloat162 h01 = __floats2bfloat162_rn(ax, ay);
    __nv_bfloat162 h23 = __floats2bfloat162_rn(az, aw);
    float rx = ax - __bfloat162float(h01.x);
    float ry = ay - __bfloat162float(h01.y);
    float rz = az - __bfloat162float(h23.x);
    float rw = aw - __bfloat162float(h23.y);
    size_t o = (size_t)gi*32 + c4*2;
    g_a1hi[o]   = *(uint*)&h01;
    g_a1hi[o+1] = *(uint*)&h23;
    g_a1lo[o]   = pbf2(rx, ry);
    g_a1lo[o+1] = pbf2(rz, rw);
}

// layer2 agg: emits bf16 hi/lo split for mma gemm2
__global__ __launch_bounds__(256) void k_agg2(const int* __restrict__ knn){
    const int TPN = H2/4;         // 32
    const int NPB = 256/TPN;      // 8
    __shared__ int sidx[NPB][KNB];
    int t = threadIdx.x;
    int n0 = blockIdx.x*NPB;
    if (t < NPB*KNB) sidx[t>>4][t&15] = knn[(size_t)(n0 + (t>>4))*KNB + (t&15)];
    __syncthreads();
    int nl = t / TPN; int c4 = t % TPN;
    int gi = n0 + nl;
    int base = (gi >> 13) * NN;
    const float4* pre = (const float4*)g_pre2;
    float4 sc = ((const float4*)g_bn2)[c4];
    float4 sh = ((const float4*)g_bn2)[TPN + c4];
    float4 p = pre[(size_t)gi*TPN + c4];
    float ax = fmaxf(fmaf(p.x, sc.x, sh.x), 0.f);
    float ay = fmaxf(fmaf(p.y, sc.y, sh.y), 0.f);
    float az = fmaxf(fmaf(p.z, sc.z, sh.z), 0.f);
    float aw = fmaxf(fmaf(p.w, sc.w, sh.w), 0.f);
    #pragma unroll
    for (int k=0;k<KNB;k++){
        int nb = base + sidx[nl][k];
        float4 q = pre[(size_t)nb*TPN + c4];
        ax += fmaxf(fmaf(q.x, sc.x, sh.x), 0.f);
        ay += fmaxf(fmaf(q.y, sc.y, sh.y), 0.f);
        az += fmaxf(fmaf(q.z, sc.z, sh.z), 0.f);
        aw += fmaxf(fmaf(q.w, sc.w, sh.w), 0.f);
    }
    const float s = 1.f/17.f;
    ax*=s; ay*=s; az*=s; aw*=s;
    __nv_bfloat162 h01 = __floats2bfloat162_rn(ax, ay);
    __nv_bfloat162 h23 = __floats2bfloat162_rn(az, aw);
    float rx = ax - __bfloat162float(h01.x);
    float ry = ay - __bfloat162float(h01.y);
    float rz = az - __bfloat162float(h23.x);
    float rw = aw - __bfloat162float(h23.y);
    size_t o = (size_t)gi*64 + c4*2;
    g_a2hi[o]   = *(uint*)&h01;
    g_a2hi[o+1] = *(uint*)&h23;
    g_a2lo[o]   = pbf2(rx, ry);
    g_a2lo[o+1] = pbf2(rz, rw);
}

// ---------------- gemm1: mma bf16 split (128 nodes x 128 cols, K=64) ----------------
// writes pre2 (no bias; bias cancels in BN) + sum/sq stats
#define AH1_OFF 0u
#define AL1_OFF 18432u
#define BH1_OFF 36864u
#define BL1_OFF 55296u
#define S1SUM_OFF 73728u
#define S1SQ_OFF  74240u
#define G1_SMEM   74752

__global__ void __launch_bounds__(256) k_gemm1_mma(){
    extern __shared__ __align__(16) char sm[];
    uint sb = smem_u32(sm);
    int t = threadIdx.x, lane = t & 31, wid = t >> 5;
    int wm = wid >> 2, wn = wid & 3;
    int node0 = blockIdx.x*128;

    float* ssum = (float*)(sm + S1SUM_OFF);
    float* ssq  = (float*)(sm + S1SQ_OFF);

    // load A hi/lo (128 rows x 64 bf16 = 128B/row, stride 144B)
    {
        int row = t >> 1, half = t & 1;
        const uint4* ph = (const uint4*)(g_a1hi + (size_t)(node0+row)*32) + half*4;
        const uint4* pl = (const uint4*)(g_a1lo + (size_t)(node0+row)*32) + half*4;
        uint4* dh = (uint4*)(sm + AH1_OFF + row*144 + half*64);
        uint4* dl = (uint4*)(sm + AL1_OFF + row*144 + half*64);
        #pragma unroll
        for (int i=0;i<4;i++){ dh[i] = ph[i]; dl[i] = pl[i]; }
    }
    // load B (w1^T: 128 cols x 64 k = 128B/row, stride 144B)
    {
        int col = t >> 1, half = t & 1;
        const uint4* ph = (const uint4*)((const char*)g_w1hi + (size_t)col*128) + half*4;
        const uint4* pl = (const uint4*)((const char*)g_w1lo + (size_t)col*128) + half*4;
        uint4* dh = (uint4*)(sm + BH1_OFF + col*144 + half*64);
        uint4* dl = (uint4*)(sm + BL1_OFF + col*144 + half*64);
        #pragma unroll
        for (int i=0;i<4;i++){ dh[i] = ph[i]; dl[i] = pl[i]; }
    }
    if (t < 128){ ssum[t]=0.f; ssq[t]=0.f; }
    __syncthreads();

    uint aBase = sb + AH1_OFF + (uint)((wm*64 + (lane & 15))*144 + (lane >> 4)*16);
    uint bBase = sb + BH1_OFF + (uint)((wn*32 + (lane & 7) + ((lane >> 4) & 1)*8)*144 + ((lane >> 3) & 1)*16);

    float acc[4][4][4];
    #pragma unroll
    for (int mi=0;mi<4;mi++)
        #pragma unroll
        for (int j=0;j<4;j++)
            #pragma unroll
            for (int r=0;r<4;r++) acc[mi][j][r] = 0.f;

    #pragma unroll
    for (int ks=0; ks<4; ks++){
        uint bh[8], bl[8];
        ldm4(bh,   bBase + ks*32);
        ldm4(bh+4, bBase + 16*144 + ks*32);
        ldm4(bl,   bBase + (BL1_OFF-BH1_OFF) + ks*32);
        ldm4(bl+4, bBase + (BL1_OFF-BH1_OFF) + 16*144 + ks*32);
        #pragma unroll
        for (int mi=0; mi<4; mi++){
            uint ah[4], al[4];
            ldm4(ah, aBase + mi*16*144 + ks*32);
            ldm4(al, aBase + (AL1_OFF-AH1_OFF) + mi*16*144 + ks*32);
            #pragma unroll
            for (int j=0;j<4;j++){
                mma16816(acc[mi][j], ah, bh[2*j], bh[2*j+1]);
                mma16816(acc[mi][j], al, bh[2*j], bh[2*j+1]);
                mma16816(acc[mi][j], ah, bl[2*j], bl[2*j+1]);
            }
        }
    }

    // write pre2 (fp32) + stats
    #pragma unroll
    for (int mi=0;mi<4;mi++){
        int r0 = node0 + wm*64 + mi*16 + (lane >> 2);
        #pragma unroll
        for (int j=0;j<4;j++){
            int c0 = wn*32 + j*8 + (lane & 3)*2;
            *(float2*)&g_pre2[(size_t)r0*H2 + c0]     = make_float2(acc[mi][j][0], acc[mi][j][1]);
            *(float2*)&g_pre2[(size_t)(r0+8)*H2 + c0] = make_float2(acc[mi][j][2], acc[mi][j][3]);
        }
    }
    #pragma unroll
    for (int j=0;j<4;j++){
        #pragma unroll
        for (int p=0;p<2;p++){
            float s=0.f, qq=0.f;
            #pragma unroll
            for (int mi=0;mi<4;mi++){
                #pragma unroll
                for (int r=0;r<2;r++){
                    float v = acc[mi][j][2*r+p];
                    s += v; qq = fmaf(v, v, qq);
                }
            }
            #pragma unroll
            for (int o=4;o<32;o<<=1){
                s  += __shfl_xor_sync(0xffffffffu, s, o);
                qq += __shfl_xor_sync(0xffffffffu, qq, o);
            }
            if (lane < 4){
                int colq = wn*32 + j*8 + lane*2 + p;
                atomicAdd(&ssum[colq], s);
                atomicAdd(&ssq[colq], qq);
            }
        }
    }
    __syncthreads();
    if (t < 128){
        atomicAdd(&g_sum2[t], ssum[t]);
        atomicAdd(&g_sq2[t], ssq[t]);
    }
}

// ---------------- gemm2: mma bf16 split (128 nodes x 512 cols, K=128) ----------------
#define AH_OFF 0u
#define AL_OFF 34816u
#define BH_OFF 69632u
#define BL_OFF 104448u
#define SSUM_OFF 139264u
#define SSQ_OFF  139776u
#define SMX_OFF  140288u
#define SMN_OFF  140800u
#define G2_SMEM  141312

__global__ void __launch_bounds__(256) k_gemm2_mma(){
    extern __shared__ __align__(16) char sm[];
    uint sb = smem_u32(sm);
    int t = threadIdx.x, lane = t & 31, wid = t >> 5;
    int wm = wid >> 2, wn = wid & 3;
    int node0 = blockIdx.x*128;
    int batch = blockIdx.x >> 6;

    float* ssum = (float*)(sm + SSUM_OFF);
    float* ssq  = (float*)(sm + SSQ_OFF);
    uint*  smx  = (uint*)(sm + SMX_OFF);
    uint*  smn  = (uint*)(sm + SMN_OFF);

    // load A hi/lo (128 rows x 128 bf16 = 256B/row, stride 272B)
    {
        int row = t >> 1, half = t & 1;
        const uint4* ph = (const uint4*)(g_a2hi + (size_t)(node0+row)*64) + half*8;
        const uint4* pl = (const uint4*)(g_a2lo + (size_t)(node0+row)*64) + half*8;
        uint4* dh = (uint4*)(sm + AH_OFF + row*272 + half*128);
        uint4* dl = (uint4*)(sm + AL_OFF + row*272 + half*128);
        #pragma unroll
        for (int i=0;i<8;i++){ dh[i] = ph[i]; dl[i] = pl[i]; }
    }

    uint aBase = sb + AH_OFF + (uint)((wm*64 + (lane & 15))*272 + (lane >> 4)*16);
    uint bBase = sb + BH_OFF + (uint)((wn*32 + (lane & 7) + ((lane >> 4) & 1)*8)*272 + ((lane >> 3) & 1)*16);

    for (int q = 0; q < 4; q++){
        int cb = q*128;
        {
            int col = t >> 1, half = t & 1;
            const uint4* ph = (const uint4*)((const char*)g_w2hi + (size_t)(cb+col)*256) + half*8;
            const uint4* pl = (const uint4*)((const char*)g_w2lo + (size_t)(cb+col)*256) + half*8;
            uint4* dh = (uint4*)(sm + BH_OFF + col*272 + half*128);
            uint4* dl = (uint4*)(sm + BL_OFF + col*272 + half*128);
            #pragma unroll
            for (int i=0;i<8;i++){ dh[i] = ph[i]; dl[i] = pl[i]; }
        }
        if (t < 128){ ssum[t]=0.f; ssq[t]=0.f; smx[t]=0u; smn[t]=0xFFFFFFFFu; }
        __syncthreads();

        float acc[4][4][4];
        #pragma unroll
        for (int mi=0;mi<4;mi++)
            #pragma unroll
            for (int j=0;j<4;j++)
                #pragma unroll
                for (int r=0;r<4;r++) acc[mi][j][r] = 0.f;

        #pragma unroll
        for (int ks=0; ks<8; ks++){
            uint bh[8], bl[8];
            ldm4(bh,   bBase + ks*32);
            ldm4(bh+4, bBase + 16*272 + ks*32);
            ldm4(bl,   bBase + (BL_OFF-BH_OFF) + ks*32);
            ldm4(bl+4, bBase + (BL_OFF-BH_OFF) + 16*272 + ks*32);
            #pragma unroll
            for (int mi=0; mi<4; mi++){
                uint ah[4], al[4];
                ldm4(ah, aBase + mi*16*272 + ks*32);
                ldm4(al, aBase + (AL_OFF-AH_OFF) + mi*16*272 + ks*32);
                #pragma unroll
                for (int j=0;j<4;j++){
                    mma16816(acc[mi][j], ah, bh[2*j], bh[2*j+1]);
                    mma16816(acc[mi][j], al, bh[2*j], bh[2*j+1]);
                    mma16816(acc[mi][j], ah, bl[2*j], bl[2*j+1]);
                }
            }
        }

        // epilogue: per-column stats only
        #pragma unroll
        for (int j=0;j<4;j++){
            #pragma unroll
            for (int p=0;p<2;p++){
                float s=0.f, qq=0.f, mx=-3.402823466e38f, mn=3.402823466e38f;
                #pragma unroll
                for (int mi=0;mi<4;mi++){
                    #pragma unroll
                    for (int r=0;r<2;r++){
                        float v = acc[mi][j][2*r+p];
                        s += v; qq = fmaf(v, v, qq);
                        mx = fmaxf(mx, v); mn = fminf(mn, v);
                    }
                }
                #pragma unroll
                for (int o=4;o<32;o<<=1){
                    s  += __shfl_xor_sync(0xffffffffu, s, o);
                    qq += __shfl_xor_sync(0xffffffffu, qq, o);
                    mx = fmaxf(mx, __shfl_xor_sync(0xffffffffu, mx, o));
                    mn = fminf(mn, __shfl_xor_sync(0xffffffffu, mn, o));
                }
                if (lane < 4){
                    int colq = wn*32 + j*8 + lane*2 + p;
                    atomicAdd(&ssum[colq], s);
                    atomicAdd(&ssq[colq], qq);
                    atomicMax(&smx[colq], fkey(mx));
                    atomicMin(&smn[colq], fkey(mn));
                }
            }
        }
        __syncthreads();
        if (t < 128){
            atomicAdd(&g_sum3[cb+t], ssum[t]);
            atomicAdd(&g_sq3[cb+t], ssq[t]);
            atomicMax(&g_maxk[batch*H1 + cb + t], smx[t]);
            atomicMin(&g_mink[batch*H1 + cb + t], smn[t]);
        }
        __syncthreads();
    }
}

// finalize BN3 + pooled (bias cancels in BN -> dropped)
__global__ void k_fin3pool(const float* __restrict__ g, const float* __restrict__ be){
    int c = threadIdx.x;
    int b = blockIdx.x;
    float invM = 1.f/(float)MTOT;
    float s = g_sum3[c]*invM;
    float q = g_sq3[c]*invM;
    float v = fmaxf(q - s*s, 0.f);
    float sc = g[c]*rsqrtf(v+EPSBN);
    float sh = fmaf(-s, sc, be[c]);
    float mx = keyf(g_maxk[b*H1+c]);
    float mn = keyf(g_mink[b*H1+c]);
    float val = (sc >= 0.f) ? fmaf(mx, sc, sh) : fmaf(mn, sc, sh);
    g_pool[b*H1+c] = fmaxf(val, 0.f);
}

// e2 linear: pre4[b] = pool[b] @ W + bias   (block per batch)
__global__ __launch_bounds__(512) void k_e2(const float* __restrict__ W, const float* __restrict__ bias){
    __shared__ float sp[H1];
    int b = blockIdx.x, c = threadIdx.x;
    sp[c] = g_pool[b*H1 + c];
    __syncthreads();
    float acc = bias[c];
    #pragma unroll 4
    for (int f=0; f<H1; f++) acc = fmaf(sp[f], W[(size_t)f*H1 + c], acc);
    g_pre4[b*H1 + c] = acc;
}

// e2 BN(M=16)+ReLU -> code; decoder per-batch dots; analytic d1 BN params
__global__ __launch_bounds__(512) void k_code2(
    const float* __restrict__ eg, const float* __restrict__ ebe,
    const float* __restrict__ d1w, const float* __restrict__ d1b,
    const float* __restrict__ d1g, const float* __restrict__ d1be,
    const float* __restrict__ d2w, const float* __restrict__ d2b)
{
    __shared__ float scm[BB*H1];
    int t = threadIdx.x;
    float vals[16]; float s = 0.f;
    #pragma unroll
    for (int b=0;b<16;b++){ vals[b]=g_pre4[b*H1+t]; s+=vals[b]; }
    float m = s*(1.f/16.f);
    float q = 0.f;
    #pragma unroll
    for (int b=0;b<16;b++){ float d=vals[b]-m; q+=d*d; }
    float scl = eg[t]*rsqrtf(q*(1.f/16.f)+EPSBN);
    float sh = ebe[t];
    #pragma unroll
    for (int b=0;b<16;b++) scm[b*H1+t] = fmaxf(fmaf(vals[b]-m, scl, sh), 0.f);
    __syncthreads();

    int w = t>>5, lane = t&31;
    if (w < 6){
        for (int d = w*16; d < w*16+16; d++){
            int layer = d/48; int r = d%48; int b = r/3; int c = r%3;
            const float* Wd = layer ? d2w : d1w;
            float p = 0.f;
            for (int f=lane; f<H1; f+=32) p = fmaf(scm[b*H1+f], Wd[f*3+c], p);
            #pragma unroll
            for (int o=16;o;o>>=1) p += __shfl_xor_sync(0xffffffffu, p, o);
            if (lane==0){
                if (layer) g_dc2[b*3+c] = p + d2b[c];
                else       g_dc1[b*3+c] = p + d1b[c];
            }
        }
    }
    __syncthreads();
    if (w < 3){
        float wx = d1w[1536 + w], wy = d1w[1539 + w];
        float sG = 0.f;
        for (int n=lane; n<NN; n+=32){
            int ix = n/65, iy = n - ix*65;
            float gx = 1.f + ix*(119.f/128.f);
            float gy = 1.f + iy*(59.f/64.f);
            sG += gx*wx + gy*wy;
        }
        #pragma unroll
        for (int o=16;o;o>>=1) sG += __shfl_xor_sync(0xffffffffu, sG, o);
        float mG = sG*(1.f/8192.f);
        float qG = 0.f;
        for (int n=lane; n<NN; n+=32){
            int ix = n/65, iy = n - ix*65;
            float gx = 1.f + ix*(119.f/128.f);
            float gy = 1.f + iy*(59.f/64.f);
            float d = gx*wx + gy*wy - mG;
            qG += d*d;
        }
        #pragma unroll
        for (int o=16;o;o>>=1) qG += __shfl_xor_sync(0xffffffffu, qG, o);
        if (lane==0){
            float vG = qG*(1.f/8192.f);
            float sA=0.f;
            #pragma unroll
            for (int b=0;b<16;b++) sA += g_dc1[b*3+w];
            float mA = sA*(1.f/16.f);
            float qA=0.f;
            #pragma unroll
            for (int b=0;b<16;b++){ float d=g_dc1[b*3+w]-mA; qA+=d*d; }
            float vA = qA*(1.f/16.f);
            float mean = mA + mG;
            float var = fmaxf(vA + vG, 0.f);
            float sc1 = d1g[w]*rsqrtf(var+EPSBN);
            g_d1p[w]=sc1; g_d1p[3+w]= d1be[w] - mean*sc1;
        }
    }
}

// per-node decode: z1 (d1+BN+ReLU), z2pre (d2), write z2pre + d2 BN stats
__global__ __launch_bounds__(256) void k_decode(const float* __restrict__ d1w, const float* __restrict__ d2w){
    __shared__ float ss[3], sq_[3];
    int t = threadIdx.x;
    if (t<3){ ss[t]=0.f; sq_[t]=0.f; }
    __syncthreads();
    int gi = blockIdx.x*256 + t;
    int n = gi & (NN-1);
    int b = gi >> 13;
    int ix = n/65, iy = n - ix*65;
    float gx = 1.f + ix*(119.f/128.f);
    float gy = 1.f + iy*(59.f/64.f);
    float z1[3];
    #pragma unroll
    for (int c=0;c<3;c++){
        float pre = g_dc1[b*3+c] + gx*d1w[1536+c] + gy*d1w[1539+c];
        z1[c] = fmaxf(fmaf(pre, g_d1p[c], g_d1p[3+c]), 0.f);
    }
    float v[3];
    #pragma unroll
    for (int c=0;c<3;c++){
        v[c] = g_dc2[b*3+c] + z1[0]*d2w[1536+c] + z1[1]*d2w[1539+c] + z1[2]*d2w[1542+c];
        g_z2[(size_t)gi*3+c] = v[c];
    }
    int lane = t & 31;
    #pragma unroll
    for (int c=0;c<3;c++){
        float sv = v[c], qv = v[c]*v[c];
        #pragma unroll
        for (int o=16;o;o>>=1){ sv += __shfl_xor_sync(0xffffffffu, sv, o); qv += __shfl_xor_sync(0xffffffffu, qv, o); }
        if (lane==0){ atomicAdd(&ss[c], sv); atomicAdd(&sq_[c], qv); }
    }
    __syncthreads();
    if (t<3){ atomicAdd(&g_sumd[t], ss[t]); atomicAdd(&g_sqd[t], sq_[t]); }
}

__global__ void k_out(float* __restrict__ out, const float* __restrict__ g, const float* __restrict__ be){
    int i = blockIdx.x*blockDim.x + threadIdx.x;
    if (i >= MTOT*3) return;
    int c = i % 3;
    float invM = 1.f/(float)MTOT;
    float m = g_sumd[c]*invM;
    float v = fmaxf(g_sqd[c]*invM - m*m, 0.f);
    float sc = g[c]*rsqrtf(v+EPSBN);
    out[i] = fmaxf(fmaf(g_z2[i]-m, sc, be[c]), 0.f);
}

// ---------------- launch ----------------
extern "C" void kernel_launch(void* const* d_in, const int* in_sizes, int n_in,
                              void* d_out, int out_size)
{
    const float* data = (const float*)d_in[0];
    const int*   knn  = (const int*)  d_in[1];
    const float* e1w  = (const float*)d_in[2];
    const float* e1b  = (const float*)d_in[3];
    const float* e1g  = (const float*)d_in[4];
    const float* e1be = (const float*)d_in[5];
    const float* gc1w = (const float*)d_in[6];
    const float* g1g  = (const float*)d_in[8];
    const float* g1be = (const float*)d_in[9];
    const float* gc2w = (const float*)d_in[10];
    const float* g2g  = (const float*)d_in[12];
    const float* g2be = (const float*)d_in[13];
    const float* e2w  = (const float*)d_in[14];
    const float* e2b  = (const float*)d_in[15];
    const float* e2g  = (const float*)d_in[16];
    const float* e2be = (const float*)d_in[17];
    const float* d1w  = (const float*)d_in[18];
    const float* d1b  = (const float*)d_in[19];
    const float* d1g  = (const float*)d_in[20];
    const float* d1be = (const float*)d_in[21];
    const float* d2w  = (const float*)d_in[22];
    const float* d2b  = (const float*)d_in[23];
    const float* d2g  = (const float*)d_in[24];
    const float* d2be = (const float*)d_in[25];
    float* out = (float*)d_out;

    cudaFuncSetAttribute(k_gemm1_mma, cudaFuncAttributeMaxDynamicSharedMemorySize, G1_SMEM);
    cudaFuncSetAttribute(k_gemm2_mma, cudaFuncAttributeMaxDynamicSharedMemorySize, G2_SMEM);

    k_init<<<256, 256>>>(gc1w, gc2w);
    k_cov_e1<<<MTOT/256, 256>>>(data, knn, e1w, e1b);
    k_fin<H3,1><<<1, H3>>>(e1g, e1be);
    k_agg1<<<MTOT/16, 256>>>(knn);
    k_gemm1_mma<<<MTOT/128, 256, G1_SMEM>>>();
    k_fin<H2,2><<<1, H2>>>(g1g, g1be);
    k_agg2<<<MTOT/8, 256>>>(knn);
    k_gemm2_mma<<<MTOT/128, 256, G2_SMEM>>>();
    k_fin3pool<<<BB, H1>>>(g2g, g2be);
    k_e2<<<BB, H1>>>(e2w, e2b);
    k_code2<<<1, 512>>>(e2g, e2be, d1w, d1b, d1g, d1be, d2w, d2b);
    k_decode<<<MTOT/256, 256>>>(d1w, d2w);
    k_out<<<(MTOT*3+255)/256, 256>>>(out, d2g, d2be);
}